// round 2
// baseline (speedup 1.0000x reference)
#include <cuda_runtime.h>
#include <cstdint>

#define NN 50000
#define EE 800000
#define DD 128

// Scratch (allocation-free rule: __device__ globals)
__device__ float g_agg[(size_t)NN * 128];
__device__ float g_fsum[NN * 3];
__device__ float g_cnt[NN];

__device__ __forceinline__ float silu_f(float x) {
    return x / (1.0f + __expf(-x));
}

// ---- packed fp32x2 helpers (sm_103a FFMA2 path; exact fp32 math) ----
typedef unsigned long long u64t;

__device__ __forceinline__ u64t pack2(float lo, float hi) {
    u64t r; asm("mov.b64 %0, {%1, %2};" : "=l"(r) : "f"(lo), "f"(hi)); return r;
}
__device__ __forceinline__ u64t splat2(float x) {
    u64t r; asm("mov.b64 %0, {%1, %1};" : "=l"(r) : "f"(x)); return r;
}
__device__ __forceinline__ void fma2(u64t& d, u64t a, u64t b) {
    asm("fma.rn.f32x2 %0, %1, %2, %0;" : "+l"(d) : "l"(a), "l"(b));
}
__device__ __forceinline__ float2 unpack2(u64t v) {
    float2 f; asm("mov.b64 {%0, %1}, %2;" : "=f"(f.x), "=f"(f.y) : "l"(v)); return f;
}

// strides (floats), chosen float4-aligned
#define SA_STRIDE 36
#define SH_STRIDE 132

// ---------------------------------------------------------------------------
// Edge kernel: tile of 64 edges, fused 3-GEMM chain + scatters.
// 256 threads; thread (warp,lane) owns rows warp*8..+7, cols lane*4..+3,
// accumulated as packed f32x2 pairs.
// ---------------------------------------------------------------------------
__global__ __launch_bounds__(256, 2) void edge_kernel(
    const float* __restrict__ h, const float* __restrict__ coord_diff,
    const int* __restrict__ row, const int* __restrict__ col,
    const float* __restrict__ We1, const float* __restrict__ be1,
    const float* __restrict__ We2, const float* __restrict__ be2,
    const float* __restrict__ Wc1, const float* __restrict__ bc1,
    const float* __restrict__ Wc2)
{
    extern __shared__ float sm[];
    float* sB   = sm;                      // [32][128] = 4096
    float* sA   = sB + 4096;               // [64][36]  = 2304
    float* sH   = sA + 2304;               // [64][132] = 8448
    float* sM   = sH + 8448;               // [64][132] = 8448
    float* sRad = sM + 8448;               // [64]
    float* sCoef= sRad + 64;               // [64]
    int*   sRow = (int*)(sCoef + 64);      // [64]
    int*   sCol = sRow + 64;               // [64]

    const int t    = threadIdx.x;
    const int lane = t & 31;
    const int warp = t >> 5;
    const int col0 = lane * 4;
    const int row0 = warp * 8;
    const int e0   = blockIdx.x * 64;

    if (t < 64) {
        int e = e0 + t;
        sRow[t] = row[e];
        sCol[t] = col[e];
        float cx = coord_diff[e * 3 + 0];
        float cy = coord_diff[e * 3 + 1];
        float cz = coord_diff[e * 3 + 2];
        sRad[t] = cx * cx + cy * cy + cz * cz;
    }
    __syncthreads();

    u64t acc2[8][2];

    // ---- GEMM1: [64,257] @ We1[257,128]; radial (k=256) + bias in init ----
    {
        ulonglong2 w2 = *(const ulonglong2*)(We1 + 256 * 128 + col0);
        ulonglong2 b2 = *(const ulonglong2*)(be1 + col0);
#pragma unroll
        for (int i = 0; i < 8; i++) {
            u64t rs = splat2(sRad[row0 + i]);
            acc2[i][0] = b2.x; fma2(acc2[i][0], rs, w2.x);
            acc2[i][1] = b2.y; fma2(acc2[i][1], rs, w2.y);
        }
    }

    for (int kc = 0; kc < 8; kc++) {
        __syncthreads();
        // stage weight chunk [32][128]
        {
            const float4* Wsrc = (const float4*)(We1 + kc * 32 * 128);
            float4* Bdst = (float4*)sB;
            Bdst[t]       = Wsrc[t];
            Bdst[t + 256] = Wsrc[t + 256];
            Bdst[t + 512] = Wsrc[t + 512];
            Bdst[t + 768] = Wsrc[t + 768];
        }
        // gather A chunk: 64 edges x 32 k, float4 gathers from h
#pragma unroll
        for (int it = 0; it < 2; it++) {
            int i = t + it * 256;           // 0..511
            int e  = i >> 3;
            int kq = i & 7;
            int k  = kc * 32 + kq * 4;
            const float* src = (k < 128)
                ? (h + (size_t)sRow[e] * 128 + k)
                : (h + (size_t)sCol[e] * 128 + (k - 128));
            *(float4*)(sA + e * SA_STRIDE + kq * 4) = *(const float4*)src;
        }
        __syncthreads();
#pragma unroll
        for (int k4 = 0; k4 < 8; k4++) {
            float4 a4[8];
#pragma unroll
            for (int i = 0; i < 8; i++)
                a4[i] = *(const float4*)(sA + (row0 + i) * SA_STRIDE + k4 * 4);
#pragma unroll
            for (int q = 0; q < 4; q++) {
                int kk = k4 * 4 + q;
                ulonglong2 b2 = *(const ulonglong2*)(sB + kk * 128 + col0);
#pragma unroll
                for (int i = 0; i < 8; i++) {
                    float a = (q == 0) ? a4[i].x : (q == 1) ? a4[i].y
                            : (q == 2) ? a4[i].z : a4[i].w;
                    u64t as = splat2(a);
                    fma2(acc2[i][0], as, b2.x);
                    fma2(acc2[i][1], as, b2.y);
                }
            }
        }
    }
    // silu -> sH
#pragma unroll
    for (int i = 0; i < 8; i++) {
        float2 p0 = unpack2(acc2[i][0]);
        float2 p1 = unpack2(acc2[i][1]);
        float4 v;
        v.x = silu_f(p0.x); v.y = silu_f(p0.y);
        v.z = silu_f(p1.x); v.w = silu_f(p1.y);
        *(float4*)(sH + (row0 + i) * SH_STRIDE + col0) = v;
    }

    // ---- GEMM2: m = silu(sH @ We2 + be2) ----
    {
        ulonglong2 b2 = *(const ulonglong2*)(be2 + col0);
#pragma unroll
        for (int i = 0; i < 8; i++) { acc2[i][0] = b2.x; acc2[i][1] = b2.y; }
    }
    for (int kc = 0; kc < 4; kc++) {
        __syncthreads();
        {
            const float4* Wsrc = (const float4*)(We2 + kc * 32 * 128);
            float4* Bdst = (float4*)sB;
            Bdst[t]       = Wsrc[t];
            Bdst[t + 256] = Wsrc[t + 256];
            Bdst[t + 512] = Wsrc[t + 512];
            Bdst[t + 768] = Wsrc[t + 768];
        }
        __syncthreads();
#pragma unroll
        for (int k4 = 0; k4 < 8; k4++) {
            float4 a4[8];
#pragma unroll
            for (int i = 0; i < 8; i++)
                a4[i] = *(const float4*)(sH + (row0 + i) * SH_STRIDE + kc * 32 + k4 * 4);
#pragma unroll
            for (int q = 0; q < 4; q++) {
                int kk = k4 * 4 + q;
                ulonglong2 b2 = *(const ulonglong2*)(sB + kk * 128 + col0);
#pragma unroll
                for (int i = 0; i < 8; i++) {
                    float a = (q == 0) ? a4[i].x : (q == 1) ? a4[i].y
                            : (q == 2) ? a4[i].z : a4[i].w;
                    u64t as = splat2(a);
                    fma2(acc2[i][0], as, b2.x);
                    fma2(acc2[i][1], as, b2.y);
                }
            }
        }
    }
#pragma unroll
    for (int i = 0; i < 8; i++) {
        float2 p0 = unpack2(acc2[i][0]);
        float2 p1 = unpack2(acc2[i][1]);
        float4 v;
        v.x = silu_f(p0.x); v.y = silu_f(p0.y);
        v.z = silu_f(p1.x); v.w = silu_f(p1.y);
        *(float4*)(sM + (row0 + i) * SH_STRIDE + col0) = v;
    }

    // ---- GEMM3: t = silu(sM @ Wc1 + bc1); coef = t @ Wc2 ----
    {
        ulonglong2 b2 = *(const ulonglong2*)(bc1 + col0);
#pragma unroll
        for (int i = 0; i < 8; i++) { acc2[i][0] = b2.x; acc2[i][1] = b2.y; }
    }
    for (int kc = 0; kc < 4; kc++) {
        __syncthreads();
        {
            const float4* Wsrc = (const float4*)(Wc1 + kc * 32 * 128);
            float4* Bdst = (float4*)sB;
            Bdst[t]       = Wsrc[t];
            Bdst[t + 256] = Wsrc[t + 256];
            Bdst[t + 512] = Wsrc[t + 512];
            Bdst[t + 768] = Wsrc[t + 768];
        }
        __syncthreads();
#pragma unroll
        for (int k4 = 0; k4 < 8; k4++) {
            float4 a4[8];
#pragma unroll
            for (int i = 0; i < 8; i++)
                a4[i] = *(const float4*)(sM + (row0 + i) * SH_STRIDE + kc * 32 + k4 * 4);
#pragma unroll
            for (int q = 0; q < 4; q++) {
                int kk = k4 * 4 + q;
                ulonglong2 b2 = *(const ulonglong2*)(sB + kk * 128 + col0);
#pragma unroll
                for (int i = 0; i < 8; i++) {
                    float a = (q == 0) ? a4[i].x : (q == 1) ? a4[i].y
                            : (q == 2) ? a4[i].z : a4[i].w;
                    u64t as = splat2(a);
                    fma2(acc2[i][0], as, b2.x);
                    fma2(acc2[i][1], as, b2.y);
                }
            }
        }
    }
    {
        float wc[4];
#pragma unroll
        for (int j = 0; j < 4; j++) wc[j] = Wc2[col0 + j];
#pragma unroll
        for (int i = 0; i < 8; i++) {
            float2 p0 = unpack2(acc2[i][0]);
            float2 p1 = unpack2(acc2[i][1]);
            float v = silu_f(p0.x) * wc[0] + silu_f(p0.y) * wc[1]
                    + silu_f(p1.x) * wc[2] + silu_f(p1.y) * wc[3];
#pragma unroll
            for (int o = 16; o > 0; o >>= 1) v += __shfl_xor_sync(0xffffffffu, v, o);
            if (lane == 0) sCoef[row0 + i] = v;
        }
    }
    __syncthreads();

    // ---- scatter agg += m (coalesced over d within a warp) ----
    for (int i = t; i < 64 * 128; i += 256) {
        int e = i >> 7;
        int d = i & 127;
        atomicAdd(&g_agg[(size_t)sRow[e] * 128 + d], sM[e * SH_STRIDE + d]);
    }
    // ---- force scatter ----
    if (t < 64) {
        int e = e0 + t;
        int r = sRow[t];
        float c = sCoef[t];
#pragma unroll
        for (int q = 0; q < 3; q++) {
            float v = coord_diff[e * 3 + q] * c;
            v = fminf(fmaxf(v, -100.0f), 100.0f);
            atomicAdd(&g_fsum[r * 3 + q], v);
        }
        atomicAdd(&g_cnt[r], 1.0f);
    }
}

// ---------------------------------------------------------------------------
// Node kernel: tile of 64 nodes
//   h_out = silu([h,agg] @ Wn1 + bn1) @ Wn2 + bn2
//   vel   = silu(h @ Wv1 + bv1) @ Wv2 + bv2
//   force = f_sum / max(cnt, 1)
// out layout: [vel (N)] [force (N*3)] [h_out (N*128)]
// ---------------------------------------------------------------------------
__global__ __launch_bounds__(256, 2) void node_kernel(
    const float* __restrict__ h,
    const float* __restrict__ Wn1, const float* __restrict__ bn1,
    const float* __restrict__ Wn2, const float* __restrict__ bn2,
    const float* __restrict__ Wv1, const float* __restrict__ bv1,
    const float* __restrict__ Wv2, const float* __restrict__ bv2,
    float* __restrict__ out)
{
    extern __shared__ float sm[];
    float* sB   = sm;              // 4096
    float* sA   = sB + 4096;       // 2304
    float* sH   = sA + 2304;       // 8448
    float* sVel = sH + 8448;       // 64

    const int t    = threadIdx.x;
    const int lane = t & 31;
    const int warp = t >> 5;
    const int col0 = lane * 4;
    const int row0 = warp * 8;
    const int n0   = blockIdx.x * 64;

    u64t acc2[8][2];

    // ---- GEMM1: [h,agg] @ Wn1 + bn1, K=256 ----
    {
        ulonglong2 b2 = *(const ulonglong2*)(bn1 + col0);
#pragma unroll
        for (int i = 0; i < 8; i++) { acc2[i][0] = b2.x; acc2[i][1] = b2.y; }
    }
    for (int kc = 0; kc < 8; kc++) {
        __syncthreads();
        {
            const float4* Wsrc = (const float4*)(Wn1 + kc * 32 * 128);
            float4* Bdst = (float4*)sB;
            Bdst[t]       = Wsrc[t];
            Bdst[t + 256] = Wsrc[t + 256];
            Bdst[t + 512] = Wsrc[t + 512];
            Bdst[t + 768] = Wsrc[t + 768];
        }
#pragma unroll
        for (int it = 0; it < 2; it++) {
            int i  = t + it * 256;
            int e  = i >> 3;
            int kq = i & 7;
            int n  = n0 + e;
            float4 v = make_float4(0.f, 0.f, 0.f, 0.f);
            if (n < NN) {
                int k = kc * 32 + kq * 4;
                const float* src = (k < 128)
                    ? (h + (size_t)n * 128 + k)
                    : (g_agg + (size_t)n * 128 + (k - 128));
                v = *(const float4*)src;
            }
            *(float4*)(sA + e * SA_STRIDE + kq * 4) = v;
        }
        __syncthreads();
#pragma unroll
        for (int k4 = 0; k4 < 8; k4++) {
            float4 a4[8];
#pragma unroll
            for (int i = 0; i < 8; i++)
                a4[i] = *(const float4*)(sA + (row0 + i) * SA_STRIDE + k4 * 4);
#pragma unroll
            for (int q = 0; q < 4; q++) {
                int kk = k4 * 4 + q;
                ulonglong2 b2 = *(const ulonglong2*)(sB + kk * 128 + col0);
#pragma unroll
                for (int i = 0; i < 8; i++) {
                    float a = (q == 0) ? a4[i].x : (q == 1) ? a4[i].y
                            : (q == 2) ? a4[i].z : a4[i].w;
                    u64t as = splat2(a);
                    fma2(acc2[i][0], as, b2.x);
                    fma2(acc2[i][1], as, b2.y);
                }
            }
        }
    }
#pragma unroll
    for (int i = 0; i < 8; i++) {
        float2 p0 = unpack2(acc2[i][0]);
        float2 p1 = unpack2(acc2[i][1]);
        float4 v;
        v.x = silu_f(p0.x); v.y = silu_f(p0.y);
        v.z = silu_f(p1.x); v.w = silu_f(p1.y);
        *(float4*)(sH + (row0 + i) * SH_STRIDE + col0) = v;
    }

    // ---- GEMM2: h_out = sH @ Wn2 + bn2 ----
    {
        ulonglong2 b2 = *(const ulonglong2*)(bn2 + col0);
#pragma unroll
        for (int i = 0; i < 8; i++) { acc2[i][0] = b2.x; acc2[i][1] = b2.y; }
    }
    for (int kc = 0; kc < 4; kc++) {
        __syncthreads();
        {
            const float4* Wsrc = (const float4*)(Wn2 + kc * 32 * 128);
            float4* Bdst = (float4*)sB;
            Bdst[t]       = Wsrc[t];
            Bdst[t + 256] = Wsrc[t + 256];
            Bdst[t + 512] = Wsrc[t + 512];
            Bdst[t + 768] = Wsrc[t + 768];
        }
        __syncthreads();
#pragma unroll
        for (int k4 = 0; k4 < 8; k4++) {
            float4 a4[8];
#pragma unroll
            for (int i = 0; i < 8; i++)
                a4[i] = *(const float4*)(sH + (row0 + i) * SH_STRIDE + kc * 32 + k4 * 4);
#pragma unroll
            for (int q = 0; q < 4; q++) {
                int kk = k4 * 4 + q;
                ulonglong2 b2 = *(const ulonglong2*)(sB + kk * 128 + col0);
#pragma unroll
                for (int i = 0; i < 8; i++) {
                    float a = (q == 0) ? a4[i].x : (q == 1) ? a4[i].y
                            : (q == 2) ? a4[i].z : a4[i].w;
                    u64t as = splat2(a);
                    fma2(acc2[i][0], as, b2.x);
                    fma2(acc2[i][1], as, b2.y);
                }
            }
        }
    }
    {
        float* outH = out + (size_t)4 * NN;
#pragma unroll
        for (int i = 0; i < 8; i++) {
            int n = n0 + row0 + i;
            if (n < NN) {
                float2 p0 = unpack2(acc2[i][0]);
                float2 p1 = unpack2(acc2[i][1]);
                float4 v; v.x = p0.x; v.y = p0.y; v.z = p1.x; v.w = p1.y;
                *(float4*)(outH + (size_t)n * 128 + col0) = v;
            }
        }
    }

    // ---- vel head: v1 = silu(h @ Wv1 + bv1); vel = v1 @ Wv2 + bv2 ----
    {
        ulonglong2 b2 = *(const ulonglong2*)(bv1 + col0);
#pragma unroll
        for (int i = 0; i < 8; i++) { acc2[i][0] = b2.x; acc2[i][1] = b2.y; }
    }
    for (int kc = 0; kc < 4; kc++) {
        __syncthreads();
        {
            const float4* Wsrc = (const float4*)(Wv1 + kc * 32 * 128);
            float4* Bdst = (float4*)sB;
            Bdst[t]       = Wsrc[t];
            Bdst[t + 256] = Wsrc[t + 256];
            Bdst[t + 512] = Wsrc[t + 512];
            Bdst[t + 768] = Wsrc[t + 768];
        }
#pragma unroll
        for (int it = 0; it < 2; it++) {
            int i  = t + it * 256;
            int e  = i >> 3;
            int kq = i & 7;
            int n  = n0 + e;
            float4 v = make_float4(0.f, 0.f, 0.f, 0.f);
            if (n < NN) {
                int k = kc * 32 + kq * 4;
                v = *(const float4*)(h + (size_t)n * 128 + k);
            }
            *(float4*)(sA + e * SA_STRIDE + kq * 4) = v;
        }
        __syncthreads();
#pragma unroll
        for (int k4 = 0; k4 < 8; k4++) {
            float4 a4[8];
#pragma unroll
            for (int i = 0; i < 8; i++)
                a4[i] = *(const float4*)(sA + (row0 + i) * SA_STRIDE + k4 * 4);
#pragma unroll
            for (int q = 0; q < 4; q++) {
                int kk = k4 * 4 + q;
                ulonglong2 b2 = *(const ulonglong2*)(sB + kk * 128 + col0);
#pragma unroll
                for (int i = 0; i < 8; i++) {
                    float a = (q == 0) ? a4[i].x : (q == 1) ? a4[i].y
                            : (q == 2) ? a4[i].z : a4[i].w;
                    u64t as = splat2(a);
                    fma2(acc2[i][0], as, b2.x);
                    fma2(acc2[i][1], as, b2.y);
                }
            }
        }
    }
    {
        float wv[4];
#pragma unroll
        for (int j = 0; j < 4; j++) wv[j] = Wv2[col0 + j];
#pragma unroll
        for (int i = 0; i < 8; i++) {
            float2 p0 = unpack2(acc2[i][0]);
            float2 p1 = unpack2(acc2[i][1]);
            float v = silu_f(p0.x) * wv[0] + silu_f(p0.y) * wv[1]
                    + silu_f(p1.x) * wv[2] + silu_f(p1.y) * wv[3];
#pragma unroll
            for (int o = 16; o > 0; o >>= 1) v += __shfl_xor_sync(0xffffffffu, v, o);
            if (lane == 0) sVel[row0 + i] = v;
        }
    }
    __syncthreads();

    if (t < 64) {
        int n = n0 + t;
        if (n < NN) {
            out[n] = sVel[t] + bv2[0];
            float c = g_cnt[n];
            float inv = 1.0f / fmaxf(c, 1.0f);
            out[NN + (size_t)n * 3 + 0] = g_fsum[n * 3 + 0] * inv;
            out[NN + (size_t)n * 3 + 1] = g_fsum[n * 3 + 1] * inv;
            out[NN + (size_t)n * 3 + 2] = g_fsum[n * 3 + 2] * inv;
        }
    }
}

// ---------------------------------------------------------------------------
extern "C" void kernel_launch(void* const* d_in, const int* in_sizes, int n_in,
                              void* d_out, int out_size)
{
    const float* h          = (const float*)d_in[0];
    const float* coord_diff = (const float*)d_in[1];
    const int*   row        = (const int*)  d_in[2];
    const int*   col        = (const int*)  d_in[3];
    const float* We1 = (const float*)d_in[4];
    const float* be1 = (const float*)d_in[5];
    const float* We2 = (const float*)d_in[6];
    const float* be2 = (const float*)d_in[7];
    const float* Wn1 = (const float*)d_in[8];
    const float* bn1 = (const float*)d_in[9];
    const float* Wn2 = (const float*)d_in[10];
    const float* bn2 = (const float*)d_in[11];
    const float* Wc1 = (const float*)d_in[12];
    const float* bc1 = (const float*)d_in[13];
    const float* Wc2 = (const float*)d_in[14];
    const float* Wv1 = (const float*)d_in[15];
    const float* bv1 = (const float*)d_in[16];
    const float* Wv2 = (const float*)d_in[17];
    const float* bv2 = (const float*)d_in[18];
    float* out = (float*)d_out;

    void *aggp, *fsump, *cntp;
    cudaGetSymbolAddress(&aggp, g_agg);
    cudaGetSymbolAddress(&fsump, g_fsum);
    cudaGetSymbolAddress(&cntp, g_cnt);
    cudaMemsetAsync(aggp,  0, (size_t)NN * 128 * sizeof(float));
    cudaMemsetAsync(fsump, 0, (size_t)NN * 3 * sizeof(float));
    cudaMemsetAsync(cntp,  0, (size_t)NN * sizeof(float));

    const size_t smE = (size_t)(4096 + 2304 + 8448 + 8448 + 64 + 64 + 64 + 64) * sizeof(float);
    cudaFuncSetAttribute(edge_kernel, cudaFuncAttributeMaxDynamicSharedMemorySize, (int)smE);
    edge_kernel<<<EE / 64, 256, smE>>>(h, coord_diff, row, col,
                                       We1, be1, We2, be2, Wc1, bc1, Wc2);

    const size_t smN = (size_t)(4096 + 2304 + 8448 + 64) * sizeof(float);
    cudaFuncSetAttribute(node_kernel, cudaFuncAttributeMaxDynamicSharedMemorySize, (int)smN);
    node_kernel<<<(NN + 63) / 64, 256, smN>>>(h, Wn1, bn1, Wn2, bn2,
                                              Wv1, bv1, Wv2, bv2, out);
}

// round 3
// speedup vs baseline: 1.5700x; 1.5700x over previous
#include <cuda_runtime.h>
#include <cstdint>

#define NN 50000
#define EE 800000
#define DD 128

// Scratch (allocation-free rule: __device__ globals)
__device__ float g_agg[(size_t)NN * 128];
__device__ float g_fsum[NN * 3];
__device__ float g_cnt[NN];

__device__ __forceinline__ float silu_f(float x) {
    return x / (1.0f + __expf(-x));
}

// ---------------------------------------------------------------------------
// Edge kernel: per tile of 64 edges, fused
//   h1 = silu([h[row],h[col],radial] @ We1 + be1)
//   m  = silu(h1 @ We2 + be2)          (m overwrites h1 in smem: rows are
//   t  = silu(m @ Wc1 + bc1); coef = t @ Wc2        warp-private)
//   atomics: agg[row]+=m ; f_sum[row]+=clip(coord_diff*coef) ; cnt[row]+=1
// 256 threads; thread (warp,lane) owns rows warp*8..+7, cols lane*4..+3.
// smem ~58KB -> 3 CTAs/SM.
// ---------------------------------------------------------------------------
__global__ __launch_bounds__(256, 3) void edge_kernel(
    const float* __restrict__ h, const float* __restrict__ coord_diff,
    const int* __restrict__ row, const int* __restrict__ col,
    const float* __restrict__ We1, const float* __restrict__ be1,
    const float* __restrict__ We2, const float* __restrict__ be2,
    const float* __restrict__ Wc1, const float* __restrict__ bc1,
    const float* __restrict__ Wc2)
{
    extern __shared__ float sm[];
    float* sB   = sm;                  // [32][128] = 4096
    float* sA   = sB + 4096;           // [64][33]  = 2112 (padded)
    float* sH   = sA + 2112;           // [64][132] = 8448 (h1, then m in-place)
    float* sRad = sH + 8448;           // [64]
    float* sCoef= sRad + 64;           // [64]
    int*   sRow = (int*)(sCoef + 64);  // [64]
    int*   sCol = sRow + 64;           // [64]

    const int t    = threadIdx.x;
    const int lane = t & 31;
    const int warp = t >> 5;
    const int col0 = lane * 4;
    const int row0 = warp * 8;
    const int e0   = blockIdx.x * 64;

    if (t < 64) {
        int e = e0 + t;
        sRow[t] = row[e];
        sCol[t] = col[e];
        float cx = coord_diff[e * 3 + 0];
        float cy = coord_diff[e * 3 + 1];
        float cz = coord_diff[e * 3 + 2];
        sRad[t] = cx * cx + cy * cy + cz * cz;
    }
    __syncthreads();

    float acc[8][4];

    // ---- GEMM1: [64,257] @ We1[257,128] ; radial (k=256) + bias folded into init
    {
        float w[4], b[4];
#pragma unroll
        for (int j = 0; j < 4; j++) w[j] = We1[256 * 128 + col0 + j];
#pragma unroll
        for (int j = 0; j < 4; j++) b[j] = be1[col0 + j];
#pragma unroll
        for (int i = 0; i < 8; i++) {
            float r = sRad[row0 + i];
#pragma unroll
            for (int j = 0; j < 4; j++) acc[i][j] = b[j] + r * w[j];
        }
    }

    for (int kc = 0; kc < 8; kc++) {
        __syncthreads();
        // stage weight chunk [32][128]
        {
            const float4* Wsrc = (const float4*)(We1 + kc * 32 * 128);
            float4* Bdst = (float4*)sB;
            Bdst[t]       = Wsrc[t];
            Bdst[t + 256] = Wsrc[t + 256];
            Bdst[t + 512] = Wsrc[t + 512];
            Bdst[t + 768] = Wsrc[t + 768];
        }
        // gather A chunk: 64 edges x 32 k, float4 gathers from h
#pragma unroll
        for (int it = 0; it < 2; it++) {
            int i = t + it * 256;           // 0..511
            int e  = i >> 3;
            int kq = i & 7;
            int k  = kc * 32 + kq * 4;
            const float* src = (k < 128)
                ? (h + (size_t)sRow[e] * 128 + k)
                : (h + (size_t)sCol[e] * 128 + (k - 128));
            float4 v = *(const float4*)src;
            float* dst = sA + e * 33 + kq * 4;
            dst[0] = v.x; dst[1] = v.y; dst[2] = v.z; dst[3] = v.w;
        }
        __syncthreads();
#pragma unroll
        for (int kk = 0; kk < 32; kk++) {
            float4 bv = *(const float4*)(sB + kk * 128 + col0);
#pragma unroll
            for (int i = 0; i < 8; i++) {
                float a = sA[(row0 + i) * 33 + kk];   // warp-broadcast
                acc[i][0] += a * bv.x;
                acc[i][1] += a * bv.y;
                acc[i][2] += a * bv.z;
                acc[i][3] += a * bv.w;
            }
        }
    }
    // silu -> sH
#pragma unroll
    for (int i = 0; i < 8; i++) {
        float4 v;
        v.x = silu_f(acc[i][0]); v.y = silu_f(acc[i][1]);
        v.z = silu_f(acc[i][2]); v.w = silu_f(acc[i][3]);
        *(float4*)(sH + (row0 + i) * 132 + col0) = v;
    }

    // ---- GEMM2: m = silu(sH @ We2 + be2); m overwrites sH (warp-private rows)
#pragma unroll
    for (int i = 0; i < 8; i++)
#pragma unroll
        for (int j = 0; j < 4; j++) acc[i][j] = be2[col0 + j];

    for (int kc = 0; kc < 4; kc++) {
        __syncthreads();
        const float4* Wsrc = (const float4*)(We2 + kc * 32 * 128);
        float4* Bdst = (float4*)sB;
        Bdst[t]       = Wsrc[t];
        Bdst[t + 256] = Wsrc[t + 256];
        Bdst[t + 512] = Wsrc[t + 512];
        Bdst[t + 768] = Wsrc[t + 768];
        __syncthreads();
#pragma unroll
        for (int kk = 0; kk < 32; kk++) {
            float4 bv = *(const float4*)(sB + kk * 128 + col0);
            int kg = kc * 32 + kk;
#pragma unroll
            for (int i = 0; i < 8; i++) {
                float a = sH[(row0 + i) * 132 + kg];
                acc[i][0] += a * bv.x;
                acc[i][1] += a * bv.y;
                acc[i][2] += a * bv.z;
                acc[i][3] += a * bv.w;
            }
        }
    }
    // m -> sH in place (this warp's rows only; reads for GEMM2 are complete)
#pragma unroll
    for (int i = 0; i < 8; i++) {
        float4 v;
        v.x = silu_f(acc[i][0]); v.y = silu_f(acc[i][1]);
        v.z = silu_f(acc[i][2]); v.w = silu_f(acc[i][3]);
        *(float4*)(sH + (row0 + i) * 132 + col0) = v;
    }

    // ---- GEMM3: t = silu(m @ Wc1 + bc1); coef = t @ Wc2
#pragma unroll
    for (int i = 0; i < 8; i++)
#pragma unroll
        for (int j = 0; j < 4; j++) acc[i][j] = bc1[col0 + j];

    for (int kc = 0; kc < 4; kc++) {
        __syncthreads();
        const float4* Wsrc = (const float4*)(Wc1 + kc * 32 * 128);
        float4* Bdst = (float4*)sB;
        Bdst[t]       = Wsrc[t];
        Bdst[t + 256] = Wsrc[t + 256];
        Bdst[t + 512] = Wsrc[t + 512];
        Bdst[t + 768] = Wsrc[t + 768];
        __syncthreads();
#pragma unroll
        for (int kk = 0; kk < 32; kk++) {
            float4 bv = *(const float4*)(sB + kk * 128 + col0);
            int kg = kc * 32 + kk;
#pragma unroll
            for (int i = 0; i < 8; i++) {
                float a = sH[(row0 + i) * 132 + kg];
                acc[i][0] += a * bv.x;
                acc[i][1] += a * bv.y;
                acc[i][2] += a * bv.z;
                acc[i][3] += a * bv.w;
            }
        }
    }
    {
        float wc[4];
#pragma unroll
        for (int j = 0; j < 4; j++) wc[j] = Wc2[col0 + j];
#pragma unroll
        for (int i = 0; i < 8; i++) {
            float v = silu_f(acc[i][0]) * wc[0] + silu_f(acc[i][1]) * wc[1]
                    + silu_f(acc[i][2]) * wc[2] + silu_f(acc[i][3]) * wc[3];
#pragma unroll
            for (int o = 16; o > 0; o >>= 1) v += __shfl_xor_sync(0xffffffffu, v, o);
            if (lane == 0) sCoef[row0 + i] = v;
        }
    }
    __syncthreads();   // all m rows + coef visible to all threads

    // ---- scatter agg += m (coalesced over d within a warp)
    for (int i = t; i < 64 * 128; i += 256) {
        int e = i >> 7;
        int d = i & 127;
        atomicAdd(&g_agg[(size_t)sRow[e] * 128 + d], sH[e * 132 + d]);
    }
    // ---- force scatter
    if (t < 64) {
        int e = e0 + t;
        int r = sRow[t];
        float c = sCoef[t];
#pragma unroll
        for (int q = 0; q < 3; q++) {
            float v = coord_diff[e * 3 + q] * c;
            v = fminf(fmaxf(v, -100.0f), 100.0f);
            atomicAdd(&g_fsum[r * 3 + q], v);
        }
        atomicAdd(&g_cnt[r], 1.0f);
    }
}

// ---------------------------------------------------------------------------
// Node kernel: per tile of 64 nodes (identical to the R1 version)
//   h_out = silu([h,agg] @ Wn1 + bn1) @ Wn2 + bn2
//   vel   = silu(h @ Wv1 + bv1) @ Wv2 + bv2
//   force = f_sum / max(cnt, 1)
// out layout: [vel (N)] [force (N*3)] [h_out (N*128)]
// ---------------------------------------------------------------------------
__global__ __launch_bounds__(256, 3) void node_kernel(
    const float* __restrict__ h,
    const float* __restrict__ Wn1, const float* __restrict__ bn1,
    const float* __restrict__ Wn2, const float* __restrict__ bn2,
    const float* __restrict__ Wv1, const float* __restrict__ bv1,
    const float* __restrict__ Wv2, const float* __restrict__ bv2,
    float* __restrict__ out)
{
    extern __shared__ float sm[];
    float* sB   = sm;            // 4096
    float* sA   = sB + 4096;     // 2112
    float* sH   = sA + 2112;     // 8448
    float* sVel = sH + 8448;     // 64

    const int t    = threadIdx.x;
    const int lane = t & 31;
    const int warp = t >> 5;
    const int col0 = lane * 4;
    const int row0 = warp * 8;
    const int n0   = blockIdx.x * 64;

    float acc[8][4];

    // ---- GEMM1: [h,agg] @ Wn1 + bn1, K=256
#pragma unroll
    for (int i = 0; i < 8; i++)
#pragma unroll
        for (int j = 0; j < 4; j++) acc[i][j] = bn1[col0 + j];

    for (int kc = 0; kc < 8; kc++) {
        __syncthreads();
        const float4* Wsrc = (const float4*)(Wn1 + kc * 32 * 128);
        float4* Bdst = (float4*)sB;
        Bdst[t]       = Wsrc[t];
        Bdst[t + 256] = Wsrc[t + 256];
        Bdst[t + 512] = Wsrc[t + 512];
        Bdst[t + 768] = Wsrc[t + 768];
#pragma unroll
        for (int it = 0; it < 2; it++) {
            int i  = t + it * 256;
            int e  = i >> 3;
            int kq = i & 7;
            int n  = n0 + e;
            float4 v = make_float4(0.f, 0.f, 0.f, 0.f);
            if (n < NN) {
                int k = kc * 32 + kq * 4;
                const float* src = (k < 128)
                    ? (h + (size_t)n * 128 + k)
                    : (g_agg + (size_t)n * 128 + (k - 128));
                v = *(const float4*)src;
            }
            float* dst = sA + e * 33 + kq * 4;
            dst[0] = v.x; dst[1] = v.y; dst[2] = v.z; dst[3] = v.w;
        }
        __syncthreads();
#pragma unroll
        for (int kk = 0; kk < 32; kk++) {
            float4 bv = *(const float4*)(sB + kk * 128 + col0);
#pragma unroll
            for (int i = 0; i < 8; i++) {
                float a = sA[(row0 + i) * 33 + kk];
                acc[i][0] += a * bv.x;
                acc[i][1] += a * bv.y;
                acc[i][2] += a * bv.z;
                acc[i][3] += a * bv.w;
            }
        }
    }
#pragma unroll
    for (int i = 0; i < 8; i++) {
        float4 v;
        v.x = silu_f(acc[i][0]); v.y = silu_f(acc[i][1]);
        v.z = silu_f(acc[i][2]); v.w = silu_f(acc[i][3]);
        *(float4*)(sH + (row0 + i) * 132 + col0) = v;
    }

    // ---- GEMM2: h_out = sH @ Wn2 + bn2 (no activation)
#pragma unroll
    for (int i = 0; i < 8; i++)
#pragma unroll
        for (int j = 0; j < 4; j++) acc[i][j] = bn2[col0 + j];

    for (int kc = 0; kc < 4; kc++) {
        __syncthreads();
        const float4* Wsrc = (const float4*)(Wn2 + kc * 32 * 128);
        float4* Bdst = (float4*)sB;
        Bdst[t]       = Wsrc[t];
        Bdst[t + 256] = Wsrc[t + 256];
        Bdst[t + 512] = Wsrc[t + 512];
        Bdst[t + 768] = Wsrc[t + 768];
        __syncthreads();
#pragma unroll
        for (int kk = 0; kk < 32; kk++) {
            float4 bv = *(const float4*)(sB + kk * 128 + col0);
            int kg = kc * 32 + kk;
#pragma unroll
            for (int i = 0; i < 8; i++) {
                float a = sH[(row0 + i) * 132 + kg];
                acc[i][0] += a * bv.x;
                acc[i][1] += a * bv.y;
                acc[i][2] += a * bv.z;
                acc[i][3] += a * bv.w;
            }
        }
    }
    {
        float* outH = out + (size_t)4 * NN;
#pragma unroll
        for (int i = 0; i < 8; i++) {
            int n = n0 + row0 + i;
            if (n < NN) {
                float4 v;
                v.x = acc[i][0]; v.y = acc[i][1]; v.z = acc[i][2]; v.w = acc[i][3];
                *(float4*)(outH + (size_t)n * 128 + col0) = v;
            }
        }
    }

    // ---- vel head: v1 = silu(h @ Wv1 + bv1); vel = v1 @ Wv2 + bv2
#pragma unroll
    for (int i = 0; i < 8; i++)
#pragma unroll
        for (int j = 0; j < 4; j++) acc[i][j] = bv1[col0 + j];

    for (int kc = 0; kc < 4; kc++) {
        __syncthreads();
        const float4* Wsrc = (const float4*)(Wv1 + kc * 32 * 128);
        float4* Bdst = (float4*)sB;
        Bdst[t]       = Wsrc[t];
        Bdst[t + 256] = Wsrc[t + 256];
        Bdst[t + 512] = Wsrc[t + 512];
        Bdst[t + 768] = Wsrc[t + 768];
#pragma unroll
        for (int it = 0; it < 2; it++) {
            int i  = t + it * 256;
            int e  = i >> 3;
            int kq = i & 7;
            int n  = n0 + e;
            float4 v = make_float4(0.f, 0.f, 0.f, 0.f);
            if (n < NN) {
                int k = kc * 32 + kq * 4;
                v = *(const float4*)(h + (size_t)n * 128 + k);
            }
            float* dst = sA + e * 33 + kq * 4;
            dst[0] = v.x; dst[1] = v.y; dst[2] = v.z; dst[3] = v.w;
        }
        __syncthreads();
#pragma unroll
        for (int kk = 0; kk < 32; kk++) {
            float4 bv = *(const float4*)(sB + kk * 128 + col0);
#pragma unroll
            for (int i = 0; i < 8; i++) {
                float a = sA[(row0 + i) * 33 + kk];
                acc[i][0] += a * bv.x;
                acc[i][1] += a * bv.y;
                acc[i][2] += a * bv.z;
                acc[i][3] += a * bv.w;
            }
        }
    }
    {
        float wv[4];
#pragma unroll
        for (int j = 0; j < 4; j++) wv[j] = Wv2[col0 + j];
#pragma unroll
        for (int i = 0; i < 8; i++) {
            float v = silu_f(acc[i][0]) * wv[0] + silu_f(acc[i][1]) * wv[1]
                    + silu_f(acc[i][2]) * wv[2] + silu_f(acc[i][3]) * wv[3];
#pragma unroll
            for (int o = 16; o > 0; o >>= 1) v += __shfl_xor_sync(0xffffffffu, v, o);
            if (lane == 0) sVel[row0 + i] = v;
        }
    }
    __syncthreads();

    if (t < 64) {
        int n = n0 + t;
        if (n < NN) {
            out[n] = sVel[t] + bv2[0];
            float c = g_cnt[n];
            float inv = 1.0f / fmaxf(c, 1.0f);
            out[NN + (size_t)n * 3 + 0] = g_fsum[n * 3 + 0] * inv;
            out[NN + (size_t)n * 3 + 1] = g_fsum[n * 3 + 1] * inv;
            out[NN + (size_t)n * 3 + 2] = g_fsum[n * 3 + 2] * inv;
        }
    }
}

// ---------------------------------------------------------------------------
extern "C" void kernel_launch(void* const* d_in, const int* in_sizes, int n_in,
                              void* d_out, int out_size)
{
    const float* h          = (const float*)d_in[0];
    const float* coord_diff = (const float*)d_in[1];
    const int*   row        = (const int*)  d_in[2];
    const int*   col        = (const int*)  d_in[3];
    const float* We1 = (const float*)d_in[4];
    const float* be1 = (const float*)d_in[5];
    const float* We2 = (const float*)d_in[6];
    const float* be2 = (const float*)d_in[7];
    const float* Wn1 = (const float*)d_in[8];
    const float* bn1 = (const float*)d_in[9];
    const float* Wn2 = (const float*)d_in[10];
    const float* bn2 = (const float*)d_in[11];
    const float* Wc1 = (const float*)d_in[12];
    const float* bc1 = (const float*)d_in[13];
    const float* Wc2 = (const float*)d_in[14];
    const float* Wv1 = (const float*)d_in[15];
    const float* bv1 = (const float*)d_in[16];
    const float* Wv2 = (const float*)d_in[17];
    const float* bv2 = (const float*)d_in[18];
    float* out = (float*)d_out;

    void *aggp, *fsump, *cntp;
    cudaGetSymbolAddress(&aggp, g_agg);
    cudaGetSymbolAddress(&fsump, g_fsum);
    cudaGetSymbolAddress(&cntp, g_cnt);
    cudaMemsetAsync(aggp,  0, (size_t)NN * 128 * sizeof(float));
    cudaMemsetAsync(fsump, 0, (size_t)NN * 3 * sizeof(float));
    cudaMemsetAsync(cntp,  0, (size_t)NN * sizeof(float));

    const size_t smE = (size_t)(4096 + 2112 + 8448 + 64 + 64 + 64 + 64) * sizeof(float);
    cudaFuncSetAttribute(edge_kernel, cudaFuncAttributeMaxDynamicSharedMemorySize, (int)smE);
    edge_kernel<<<EE / 64, 256, smE>>>(h, coord_diff, row, col,
                                       We1, be1, We2, be2, Wc1, bc1, Wc2);

    const size_t smN = (size_t)(4096 + 2112 + 8448 + 64) * sizeof(float);
    cudaFuncSetAttribute(node_kernel, cudaFuncAttributeMaxDynamicSharedMemorySize, (int)smN);
    node_kernel<<<(NN + 63) / 64, 256, smN>>>(h, Wn1, bn1, Wn2, bn2,
                                              Wv1, bv1, Wv2, bv2, out);
}

// round 6
// speedup vs baseline: 3.1043x; 1.9773x over previous
#include <cuda_runtime.h>
#include <cuda_bf16.h>
#include <cstdint>

#define NN 50000
#define EE 800000

// ---------------- scratch (__device__ globals; no allocs) ----------------
__device__ float g_agg[(size_t)NN * 128];
__device__ float g_fsum[NN * 3];
__device__ float g_cnt[NN];

// Weight fragments for mma.sync m16n8k16 (bf16 hi/lo), per-lane order:
//   u32 index = ((hl*16 + nt)*KT + kt)*64 + lane*2 + r
// value = bf16x2 { W[k][n], W[k+1][n] }, n = nt*8 + lane/4,
//   k = kt*16 + (lane%4)*2 + r*8 ; hl=0 -> hi part, hl=1 -> lo part
__device__ __align__(16) uint2 g_We1f[16384]; // K=256: 2*16*16*64 u32
__device__ __align__(16) uint2 g_We2f[8192];  // K=128
__device__ __align__(16) uint2 g_Wc1f[8192];  // K=128

__device__ __forceinline__ float silu_f(float x) {
    return x / (1.0f + __expf(-x));
}

__device__ __forceinline__ void split_pack(float f0, float f1, uint32_t& hi, uint32_t& lo) {
    __nv_bfloat162 bh = __floats2bfloat162_rn(f0, f1);
    float2 bf = __bfloat1622float2(bh);
    __nv_bfloat162 bl = __floats2bfloat162_rn(f0 - bf.x, f1 - bf.y);
    hi = *(uint32_t*)&bh;
    lo = *(uint32_t*)&bl;
}

__device__ __forceinline__ void mma16816(float* c, const uint32_t* a, const uint32_t* b) {
    asm volatile(
        "mma.sync.aligned.m16n8k16.row.col.f32.bf16.bf16.f32 "
        "{%0,%1,%2,%3}, {%4,%5,%6,%7}, {%8,%9}, {%0,%1,%2,%3};"
        : "+f"(c[0]), "+f"(c[1]), "+f"(c[2]), "+f"(c[3])
        : "r"(a[0]), "r"(a[1]), "r"(a[2]), "r"(a[3]), "r"(b[0]), "r"(b[1]));
}

// A stride in bf16 elements (row-major [64 edges][K]), padded for bank spread
#define SAS 264
// fp32 m stride (floats)
#define SMS 129

// ---------------- prep: weights -> bf16 hi/lo fragment order --------------
__global__ void prep_weights_f(const float* __restrict__ We1,
                               const float* __restrict__ We2,
                               const float* __restrict__ Wc1) {
    int i = blockIdx.x * blockDim.x + threadIdx.x;
    const float* W; uint32_t* out; int KT, j;
    if (i < 32768)      { W = We1; out = (uint32_t*)g_We1f; KT = 16; j = i; }
    else if (i < 49152) { W = We2; out = (uint32_t*)g_We2f; KT = 8;  j = i - 32768; }
    else if (i < 65536) { W = Wc1; out = (uint32_t*)g_Wc1f; KT = 8;  j = i - 49152; }
    else return;
    int per_hl = 16 * KT * 64;
    int hl = j / per_hl; int rem = j % per_hl;
    int nt = rem / (KT * 64); rem %= KT * 64;
    int kt = rem / 64; rem %= 64;
    int lane = rem >> 1, r = rem & 1;
    int g = lane >> 2, tig = lane & 3;
    int n = nt * 8 + g;
    int k = kt * 16 + tig * 2 + r * 8;
    float w0 = W[k * 128 + n], w1 = W[(k + 1) * 128 + n];
    __nv_bfloat162 p;
    if (hl == 0) {
        p.x = __float2bfloat16(w0);
        p.y = __float2bfloat16(w1);
    } else {
        __nv_bfloat16 h0 = __float2bfloat16(w0), h1 = __float2bfloat16(w1);
        p.x = __float2bfloat16(w0 - __bfloat162float(h0));
        p.y = __float2bfloat16(w1 - __bfloat162float(h1));
    }
    out[((hl * 16 + nt) * KT + kt) * 64 + lane * 2 + r] = *(uint32_t*)&p;
}

// ---------------- shared GEMM core: 2x4 mma tiles per warp ----------------
__device__ __forceinline__ void gemm_tiles(
    const unsigned short* __restrict__ sAh, const unsigned short* __restrict__ sAl,
    const uint2* __restrict__ Bf, int KT,
    int wm, int wn, int lane, float acc[2][4][4])
{
    const int g = lane >> 2, tig = lane & 3;
    const int m0 = wm * 32;
    for (int kt = 0; kt < KT; kt++) {
        uint32_t ah[2][4], al[2][4];
        const int kb = kt * 16 + tig * 2;
#pragma unroll
        for (int mi = 0; mi < 2; mi++) {
            const unsigned short* p0 = sAh + (m0 + mi * 16 + g) * SAS + kb;
            const unsigned short* p1 = p0 + 8 * SAS;
            ah[mi][0] = *(const uint32_t*)p0;
            ah[mi][1] = *(const uint32_t*)p1;
            ah[mi][2] = *(const uint32_t*)(p0 + 8);
            ah[mi][3] = *(const uint32_t*)(p1 + 8);
            const unsigned short* q0 = sAl + (m0 + mi * 16 + g) * SAS + kb;
            const unsigned short* q1 = q0 + 8 * SAS;
            al[mi][0] = *(const uint32_t*)q0;
            al[mi][1] = *(const uint32_t*)q1;
            al[mi][2] = *(const uint32_t*)(q0 + 8);
            al[mi][3] = *(const uint32_t*)(q1 + 8);
        }
#pragma unroll
        for (int ni = 0; ni < 4; ni++) {
            const int nt = wn * 4 + ni;
            uint2 bh = Bf[(nt * KT + kt) * 32 + lane];
            uint2 bl = Bf[((16 + nt) * KT + kt) * 32 + lane];
            uint32_t bhr[2] = {bh.x, bh.y};
            uint32_t blr[2] = {bl.x, bl.y};
            mma16816(acc[0][ni], ah[0], bhr);
            mma16816(acc[1][ni], ah[1], bhr);
            mma16816(acc[0][ni], al[0], bhr);
            mma16816(acc[1][ni], al[1], bhr);
            mma16816(acc[0][ni], ah[0], blr);
            mma16816(acc[1][ni], ah[1], blr);
        }
    }
}

// ---------------- edge kernel: 64 edges/CTA, mma.sync chain ---------------
// SMEM bytes:
#define OFF_AH 0u         // [64][SAS] bf16 hi  = 33792
#define OFF_AL 33792u     // lo                = 33792
#define OFF_M  67584u     // fp32 m [64][129]  = 33024
#define OFF_X  100608u    // misc
#define SMEM_EDGE_TOTAL 104960

__global__ __launch_bounds__(256, 2) void edge_kernel_mma(
    const float* __restrict__ h, const float* __restrict__ coord_diff,
    const int* __restrict__ row, const int* __restrict__ col,
    const float* __restrict__ We1, const float* __restrict__ be1,
    const float* __restrict__ be2,
    const float* __restrict__ bc1, const float* __restrict__ Wc2)
{
    extern __shared__ __align__(16) char smem[];
    unsigned short* sAh = (unsigned short*)(smem + OFF_AH);
    unsigned short* sAl = (unsigned short*)(smem + OFF_AL);
    float* sM    = (float*)(smem + OFF_M);
    int*   sRow  = (int*)  (smem + OFF_X);          // 256
    int*   sCol  = (int*)  (smem + OFF_X + 256);    // 256
    float* sRad  = (float*)(smem + OFF_X + 512);    // 256
    float* sCD   = (float*)(smem + OFF_X + 768);    // 768
    float* sBe1  = (float*)(smem + OFF_X + 1536);   // 512
    float* sW256 = (float*)(smem + OFF_X + 2048);   // 512
    float* sBe2  = (float*)(smem + OFF_X + 2560);   // 512
    float* sBc1  = (float*)(smem + OFF_X + 3072);   // 512
    float* sWc2  = (float*)(smem + OFF_X + 3584);   // 512
    float* sCoef = (float*)(smem + OFF_X + 4096);   // 256

    const int t    = threadIdx.x;
    const int lane = t & 31;
    const int wid  = t >> 5;
    const int wm   = wid >> 2;      // 0..1
    const int wn   = wid & 3;       // 0..3
    const int g    = lane >> 2;
    const int tig  = lane & 3;
    const int e0   = blockIdx.x * 64;

    if (t < 64) {
        int e = e0 + t;
        sRow[t] = row[e];
        sCol[t] = col[e];
        float cx = coord_diff[e * 3 + 0];
        float cy = coord_diff[e * 3 + 1];
        float cz = coord_diff[e * 3 + 2];
        sCD[t * 3 + 0] = cx; sCD[t * 3 + 1] = cy; sCD[t * 3 + 2] = cz;
        sRad[t] = cx * cx + cy * cy + cz * cz;
        sCoef[t] = 0.0f;
    }
    if (t < 128) {
        sBe1[t]  = be1[t];
        sW256[t] = We1[256 * 128 + t];
        sBe2[t]  = be2[t];
        sBc1[t]  = bc1[t];
        sWc2[t]  = Wc2[t];
    }
    __syncthreads();

    // ---- gather + bf16 split: A = [h[row], h[col]] as [64][256] ----
    for (int i = t; i < 64 * 64; i += 256) {
        int e = i >> 6;
        int k = (i & 63) * 4;
        const float* src = (k < 128)
            ? (h + (size_t)sRow[e] * 128 + k)
            : (h + (size_t)sCol[e] * 128 + (k - 128));
        float4 v = *(const float4*)src;
        uint32_t h0, l0, h1, l1;
        split_pack(v.x, v.y, h0, l0);
        split_pack(v.z, v.w, h1, l1);
        *(uint2*)(sAh + e * SAS + k) = make_uint2(h0, h1);
        *(uint2*)(sAl + e * SAS + k) = make_uint2(l0, l1);
    }
    __syncthreads();

    float acc[2][4][4];

    // ---- GEMM1: K=256 ----
#pragma unroll
    for (int a = 0; a < 2; a++)
#pragma unroll
        for (int b = 0; b < 4; b++)
#pragma unroll
            for (int c = 0; c < 4; c++) acc[a][b][c] = 0.0f;
    gemm_tiles(sAh, sAl, g_We1f, 16, wm, wn, lane, acc);
    __syncthreads();

    // ---- epilogue1: h1 = silu(D + be1 + rad*We1_row256) -> A (K=128) ----
#pragma unroll
    for (int mi = 0; mi < 2; mi++) {
        int rA = wm * 32 + mi * 16 + g;
        int rB = rA + 8;
        float radA = sRad[rA], radB = sRad[rB];
#pragma unroll
        for (int ni = 0; ni < 4; ni++) {
            int cb = wn * 32 + ni * 8 + tig * 2;
            float b0 = sBe1[cb], b1 = sBe1[cb + 1];
            float w0 = sW256[cb], w1 = sW256[cb + 1];
            uint32_t hi, lo;
            split_pack(silu_f(acc[mi][ni][0] + b0 + radA * w0),
                       silu_f(acc[mi][ni][1] + b1 + radA * w1), hi, lo);
            *(uint32_t*)(sAh + rA * SAS + cb) = hi;
            *(uint32_t*)(sAl + rA * SAS + cb) = lo;
            split_pack(silu_f(acc[mi][ni][2] + b0 + radB * w0),
                       silu_f(acc[mi][ni][3] + b1 + radB * w1), hi, lo);
            *(uint32_t*)(sAh + rB * SAS + cb) = hi;
            *(uint32_t*)(sAl + rB * SAS + cb) = lo;
        }
    }
    __syncthreads();

    // ---- GEMM2: K=128 ----
#pragma unroll
    for (int a = 0; a < 2; a++)
#pragma unroll
        for (int b = 0; b < 4; b++)
#pragma unroll
            for (int c = 0; c < 4; c++) acc[a][b][c] = 0.0f;
    gemm_tiles(sAh, sAl, g_We2f, 8, wm, wn, lane, acc);
    __syncthreads();

    // ---- epilogue2: m = silu(D + be2) -> sM fp32 + A bf16 ----
#pragma unroll
    for (int mi = 0; mi < 2; mi++) {
        int rA = wm * 32 + mi * 16 + g;
        int rB = rA + 8;
#pragma unroll
        for (int ni = 0; ni < 4; ni++) {
            int cb = wn * 32 + ni * 8 + tig * 2;
            float b0 = sBe2[cb], b1 = sBe2[cb + 1];
            float m0 = silu_f(acc[mi][ni][0] + b0);
            float m1 = silu_f(acc[mi][ni][1] + b1);
            float m2 = silu_f(acc[mi][ni][2] + b0);
            float m3 = silu_f(acc[mi][ni][3] + b1);
            sM[rA * SMS + cb] = m0;  sM[rA * SMS + cb + 1] = m1;
            sM[rB * SMS + cb] = m2;  sM[rB * SMS + cb + 1] = m3;
            uint32_t hi, lo;
            split_pack(m0, m1, hi, lo);
            *(uint32_t*)(sAh + rA * SAS + cb) = hi;
            *(uint32_t*)(sAl + rA * SAS + cb) = lo;
            split_pack(m2, m3, hi, lo);
            *(uint32_t*)(sAh + rB * SAS + cb) = hi;
            *(uint32_t*)(sAl + rB * SAS + cb) = lo;
        }
    }
    __syncthreads();

    // ---- GEMM3: K=128 ----
#pragma unroll
    for (int a = 0; a < 2; a++)
#pragma unroll
        for (int b = 0; b < 4; b++)
#pragma unroll
            for (int c = 0; c < 4; c++) acc[a][b][c] = 0.0f;
    gemm_tiles(sAh, sAl, g_Wc1f, 8, wm, wn, lane, acc);

    // ---- epilogue3: coef = sum_n silu(D + bc1) * Wc2 ----
    {
        float p[4] = {0.f, 0.f, 0.f, 0.f};   // (mi, half)
#pragma unroll
        for (int ni = 0; ni < 4; ni++) {
            int cb = wn * 32 + ni * 8 + tig * 2;
            float b0 = sBc1[cb], b1 = sBc1[cb + 1];
            float w0 = sWc2[cb], w1 = sWc2[cb + 1];
#pragma unroll
            for (int mi = 0; mi < 2; mi++) {
                p[mi * 2 + 0] += silu_f(acc[mi][ni][0] + b0) * w0
                               + silu_f(acc[mi][ni][1] + b1) * w1;
                p[mi * 2 + 1] += silu_f(acc[mi][ni][2] + b0) * w0
                               + silu_f(acc[mi][ni][3] + b1) * w1;
            }
        }
#pragma unroll
        for (int j = 0; j < 4; j++) {
            p[j] += __shfl_xor_sync(0xffffffffu, p[j], 1);
            p[j] += __shfl_xor_sync(0xffffffffu, p[j], 2);
        }
        if (tig == 0) {
#pragma unroll
            for (int j = 0; j < 4; j++) {
                int rr = wm * 32 + (j >> 1) * 16 + (j & 1) * 8 + g;
                atomicAdd(&sCoef[rr], p[j]);
            }
        }
    }
    __syncthreads();

    // ---- force scatter ----
    if (t < 64) {
        int r = sRow[t];
        float c = sCoef[t];
#pragma unroll
        for (int q = 0; q < 3; q++) {
            float v = sCD[t * 3 + q] * c;
            v = fminf(fmaxf(v, -100.0f), 100.0f);
            atomicAdd(&g_fsum[r * 3 + q], v);
        }
        atomicAdd(&g_cnt[r], 1.0f);
    }
    // ---- agg scatter (coalesced over d within warp) ----
    for (int i = t; i < 64 * 128; i += 256) {
        int e = i >> 7;
        int dd = i & 127;
        atomicAdd(&g_agg[(size_t)sRow[e] * 128 + dd], sM[e * SMS + dd]);
    }
}

// ---------------------------------------------------------------------------
// Node kernel (proven scalar version, ~182us)
// out layout: [vel (N)] [force (N*3)] [h_out (N*128)]
// ---------------------------------------------------------------------------
__global__ __launch_bounds__(256, 3) void node_kernel(
    const float* __restrict__ h,
    const float* __restrict__ Wn1, const float* __restrict__ bn1,
    const float* __restrict__ Wn2, const float* __restrict__ bn2,
    const float* __restrict__ Wv1, const float* __restrict__ bv1,
    const float* __restrict__ Wv2, const float* __restrict__ bv2,
    float* __restrict__ out)
{
    extern __shared__ float sm[];
    float* sB   = sm;            // 4096
    float* sA   = sB + 4096;     // 2112
    float* sH   = sA + 2112;     // 8448
    float* sVel = sH + 8448;     // 64

    const int t    = threadIdx.x;
    const int lane = t & 31;
    const int warp = t >> 5;
    const int col0 = lane * 4;
    const int row0 = warp * 8;
    const int n0   = blockIdx.x * 64;

    float acc[8][4];

#pragma unroll
    for (int i = 0; i < 8; i++)
#pragma unroll
        for (int j = 0; j < 4; j++) acc[i][j] = bn1[col0 + j];

    for (int kc = 0; kc < 8; kc++) {
        __syncthreads();
        const float4* Wsrc = (const float4*)(Wn1 + kc * 32 * 128);
        float4* Bdst = (float4*)sB;
        Bdst[t]       = Wsrc[t];
        Bdst[t + 256] = Wsrc[t + 256];
        Bdst[t + 512] = Wsrc[t + 512];
        Bdst[t + 768] = Wsrc[t + 768];
#pragma unroll
        for (int it = 0; it < 2; it++) {
            int i  = t + it * 256;
            int e  = i >> 3;
            int kq = i & 7;
            int n  = n0 + e;
            float4 v = make_float4(0.f, 0.f, 0.f, 0.f);
            if (n < NN) {
                int k = kc * 32 + kq * 4;
                const float* src = (k < 128)
                    ? (h + (size_t)n * 128 + k)
                    : (g_agg + (size_t)n * 128 + (k - 128));
                v = *(const float4*)src;
            }
            float* dst = sA + e * 33 + kq * 4;
            dst[0] = v.x; dst[1] = v.y; dst[2] = v.z; dst[3] = v.w;
        }
        __syncthreads();
#pragma unroll
        for (int kk = 0; kk < 32; kk++) {
            float4 bv = *(const float4*)(sB + kk * 128 + col0);
#pragma unroll
            for (int i = 0; i < 8; i++) {
                float a = sA[(row0 + i) * 33 + kk];
                acc[i][0] += a * bv.x;
                acc[i][1] += a * bv.y;
                acc[i][2] += a * bv.z;
                acc[i][3] += a * bv.w;
            }
        }
    }
#pragma unroll
    for (int i = 0; i < 8; i++) {
        float4 v;
        v.x = silu_f(acc[i][0]); v.y = silu_f(acc[i][1]);
        v.z = silu_f(acc[i][2]); v.w = silu_f(acc[i][3]);
        *(float4*)(sH + (row0 + i) * 132 + col0) = v;
    }

#pragma unroll
    for (int i = 0; i < 8; i++)
#pragma unroll
        for (int j = 0; j < 4; j++) acc[i][j] = bn2[col0 + j];

    for (int kc = 0; kc < 4; kc++) {
        __syncthreads();
        const float4* Wsrc = (const float4*)(Wn2 + kc * 32 * 128);
        float4* Bdst = (float4*)sB;
        Bdst[t]       = Wsrc[t];
        Bdst[t + 256] = Wsrc[t + 256];
        Bdst[t + 512] = Wsrc[t + 512];
        Bdst[t + 768] = Wsrc[t + 768];
        __syncthreads();
#pragma unroll
        for (int kk = 0; kk < 32; kk++) {
            float4 bv = *(const float4*)(sB + kk * 128 + col0);
            int kg = kc * 32 + kk;
#pragma unroll
            for (int i = 0; i < 8; i++) {
                float a = sH[(row0 + i) * 132 + kg];
                acc[i][0] += a * bv.x;
                acc[i][1] += a * bv.y;
                acc[i][2] += a * bv.z;
                acc[i][3] += a * bv.w;
            }
        }
    }
    {
        float* outH = out + (size_t)4 * NN;
#pragma unroll
        for (int i = 0; i < 8; i++) {
            int n = n0 + row0 + i;
            if (n < NN) {
                float4 v;
                v.x = acc[i][0]; v.y = acc[i][1]; v.z = acc[i][2]; v.w = acc[i][3];
                *(float4*)(outH + (size_t)n * 128 + col0) = v;
            }
        }
    }

#pragma unroll
    for (int i = 0; i < 8; i++)
#pragma unroll
        for (int j = 0; j < 4; j++) acc[i][j] = bv1[col0 + j];

    for (int kc = 0; kc < 4; kc++) {
        __syncthreads();
        const float4* Wsrc = (const float4*)(Wv1 + kc * 32 * 128);
        float4* Bdst = (float4*)sB;
        Bdst[t]       = Wsrc[t];
        Bdst[t + 256] = Wsrc[t + 256];
        Bdst[t + 512] = Wsrc[t + 512];
        Bdst[t + 768] = Wsrc[t + 768];
#pragma unroll
        for (int it = 0; it < 2; it++) {
            int i  = t + it * 256;
            int e  = i >> 3;
            int kq = i & 7;
            int n  = n0 + e;
            float4 v = make_float4(0.f, 0.f, 0.f, 0.f);
            if (n < NN) {
                int k = kc * 32 + kq * 4;
                v = *(const float4*)(h + (size_t)n * 128 + k);
            }
            float* dst = sA + e * 33 + kq * 4;
            dst[0] = v.x; dst[1] = v.y; dst[2] = v.z; dst[3] = v.w;
        }
        __syncthreads();
#pragma unroll
        for (int kk = 0; kk < 32; kk++) {
            float4 bv = *(const float4*)(sB + kk * 128 + col0);
#pragma unroll
            for (int i = 0; i < 8; i++) {
                float a = sA[(row0 + i) * 33 + kk];
                acc[i][0] += a * bv.x;
                acc[i][1] += a * bv.y;
                acc[i][2] += a * bv.z;
                acc[i][3] += a * bv.w;
            }
        }
    }
    {
        float wv[4];
#pragma unroll
        for (int j = 0; j < 4; j++) wv[j] = Wv2[col0 + j];
#pragma unroll
        for (int i = 0; i < 8; i++) {
            float v = silu_f(acc[i][0]) * wv[0] + silu_f(acc[i][1]) * wv[1]
                    + silu_f(acc[i][2]) * wv[2] + silu_f(acc[i][3]) * wv[3];
#pragma unroll
            for (int o = 16; o > 0; o >>= 1) v += __shfl_xor_sync(0xffffffffu, v, o);
            if (lane == 0) sVel[row0 + i] = v;
        }
    }
    __syncthreads();

    if (t < 64) {
        int n = n0 + t;
        if (n < NN) {
            out[n] = sVel[t] + bv2[0];
            float c = g_cnt[n];
            float inv = 1.0f / fmaxf(c, 1.0f);
            out[NN + (size_t)n * 3 + 0] = g_fsum[n * 3 + 0] * inv;
            out[NN + (size_t)n * 3 + 1] = g_fsum[n * 3 + 1] * inv;
            out[NN + (size_t)n * 3 + 2] = g_fsum[n * 3 + 2] * inv;
        }
    }
}

// ---------------------------------------------------------------------------
extern "C" void kernel_launch(void* const* d_in, const int* in_sizes, int n_in,
                              void* d_out, int out_size)
{
    const float* h          = (const float*)d_in[0];
    const float* coord_diff = (const float*)d_in[1];
    const int*   row        = (const int*)  d_in[2];
    const int*   col        = (const int*)  d_in[3];
    const float* We1 = (const float*)d_in[4];
    const float* be1 = (const float*)d_in[5];
    const float* We2 = (const float*)d_in[6];
    const float* be2 = (const float*)d_in[7];
    const float* Wn1 = (const float*)d_in[8];
    const float* bn1 = (const float*)d_in[9];
    const float* Wn2 = (const float*)d_in[10];
    const float* bn2 = (const float*)d_in[11];
    const float* Wc1 = (const float*)d_in[12];
    const float* bc1 = (const float*)d_in[13];
    const float* Wc2 = (const float*)d_in[14];
    const float* Wv1 = (const float*)d_in[15];
    const float* bv1 = (const float*)d_in[16];
    const float* Wv2 = (const float*)d_in[17];
    const float* bv2 = (const float*)d_in[18];
    float* out = (float*)d_out;

    void *aggp, *fsump, *cntp;
    cudaGetSymbolAddress(&aggp, g_agg);
    cudaGetSymbolAddress(&fsump, g_fsum);
    cudaGetSymbolAddress(&cntp, g_cnt);
    cudaMemsetAsync(aggp,  0, (size_t)NN * 128 * sizeof(float));
    cudaMemsetAsync(fsump, 0, (size_t)NN * 3 * sizeof(float));
    cudaMemsetAsync(cntp,  0, (size_t)NN * sizeof(float));

    prep_weights_f<<<256, 256>>>(We1, We2, Wc1);

    cudaFuncSetAttribute(edge_kernel_mma, cudaFuncAttributeMaxDynamicSharedMemorySize,
                         SMEM_EDGE_TOTAL);
    edge_kernel_mma<<<EE / 64, 256, SMEM_EDGE_TOTAL>>>(
        h, coord_diff, row, col, We1, be1, be2, bc1, Wc2);

    const size_t smN = (size_t)(4096 + 2112 + 8448 + 64) * sizeof(float);
    cudaFuncSetAttribute(node_kernel, cudaFuncAttributeMaxDynamicSharedMemorySize, (int)smN);
    node_kernel<<<(NN + 63) / 64, 256, smN>>>(h, Wn1, bn1, Wn2, bn2,
                                              Wv1, bv1, Wv2, bv2, out);
}

// round 7
// speedup vs baseline: 4.0980x; 1.3201x over previous
#include <cuda_runtime.h>
#include <cuda_bf16.h>
#include <cstdint>

#define NN 50000
#define EE 800000

// ---------------- scratch (__device__ globals; no allocs) ----------------
__device__ float g_agg[(size_t)NN * 128];
__device__ float g_fsum[NN * 3];
__device__ float g_cnt[NN];
__device__ float g_P1[(size_t)NN * 128];   // h @ We1[0:128,:]
__device__ float g_P2[(size_t)NN * 128];   // h @ We1[128:256,:]

// Weight fragments for mma.sync m16n8k16 (bf16 hi/lo), per-lane order:
//   u32 index = ((hl*16 + nt)*KT + kt)*64 + lane*2 + r
// value = bf16x2 { W[k][n], W[k+1][n] }, n = nt*8 + lane/4,
//   k = kt*16 + (lane%4)*2 + r*8 ; hl=0 -> hi part, hl=1 -> lo part
__device__ __align__(16) uint2 g_We1f[16384]; // K=256
__device__ __align__(16) uint2 g_We2f[8192];  // K=128
__device__ __align__(16) uint2 g_Wc1f[8192];  // K=128

__device__ __forceinline__ float silu_f(float x) {
    return x / (1.0f + __expf(-x));
}

__device__ __forceinline__ void split_pack(float f0, float f1, uint32_t& hi, uint32_t& lo) {
    __nv_bfloat162 bh = __floats2bfloat162_rn(f0, f1);
    float2 bf = __bfloat1622float2(bh);
    __nv_bfloat162 bl = __floats2bfloat162_rn(f0 - bf.x, f1 - bf.y);
    hi = *(uint32_t*)&bh;
    lo = *(uint32_t*)&bl;
}

__device__ __forceinline__ void mma16816(float* c, const uint32_t* a, const uint32_t* b) {
    asm volatile(
        "mma.sync.aligned.m16n8k16.row.col.f32.bf16.bf16.f32 "
        "{%0,%1,%2,%3}, {%4,%5,%6,%7}, {%8,%9}, {%0,%1,%2,%3};"
        : "+f"(c[0]), "+f"(c[1]), "+f"(c[2]), "+f"(c[3])
        : "r"(a[0]), "r"(a[1]), "r"(a[2]), "r"(a[3]), "r"(b[0]), "r"(b[1]));
}

// A stride in bf16 elements for K=128 tiles (row-major [64][K]); bank-spread ok
#define SAS 136
// fp32 m stride (floats)
#define SMS 129

// ---------------- prep: weights -> bf16 hi/lo fragment order --------------
__global__ void prep_weights_f(const float* __restrict__ We1,
                               const float* __restrict__ We2,
                               const float* __restrict__ Wc1) {
    int i = blockIdx.x * blockDim.x + threadIdx.x;
    const float* W; uint32_t* out; int KT, j;
    if (i < 32768)      { W = We1; out = (uint32_t*)g_We1f; KT = 16; j = i; }
    else if (i < 49152) { W = We2; out = (uint32_t*)g_We2f; KT = 8;  j = i - 32768; }
    else if (i < 65536) { W = Wc1; out = (uint32_t*)g_Wc1f; KT = 8;  j = i - 49152; }
    else return;
    int per_hl = 16 * KT * 64;
    int hl = j / per_hl; int rem = j % per_hl;
    int nt = rem / (KT * 64); rem %= KT * 64;
    int kt = rem / 64; rem %= 64;
    int lane = rem >> 1, r = rem & 1;
    int g = lane >> 2, tig = lane & 3;
    int n = nt * 8 + g;
    int k = kt * 16 + tig * 2 + r * 8;
    float w0 = W[k * 128 + n], w1 = W[(k + 1) * 128 + n];
    __nv_bfloat162 p;
    if (hl == 0) {
        p.x = __float2bfloat16(w0);
        p.y = __float2bfloat16(w1);
    } else {
        __nv_bfloat16 h0 = __float2bfloat16(w0), h1 = __float2bfloat16(w1);
        p.x = __float2bfloat16(w0 - __bfloat162float(h0));
        p.y = __float2bfloat16(w1 - __bfloat162float(h1));
    }
    out[((hl * 16 + nt) * KT + kt) * 64 + lane * 2 + r] = *(uint32_t*)&p;
}

// ---------------- shared GEMM core: 2x4 mma tiles per warp ----------------
// A in smem [64][SAS] (local K index 0..16*ktn-1); B fragments global,
// kt0 = global k-tile offset into Bf (whose layout spans KTtot tiles).
__device__ __forceinline__ void gemm_tiles(
    const unsigned short* __restrict__ sAh, const unsigned short* __restrict__ sAl,
    const uint2* __restrict__ Bf, int KTtot, int kt0, int ktn,
    int wm, int wn, int lane, float acc[2][4][4])
{
    const int g = lane >> 2, tig = lane & 3;
    const int m0 = wm * 32;
    for (int kti = 0; kti < ktn; kti++) {
        uint32_t ah[2][4], al[2][4];
        const int kb = kti * 16 + tig * 2;
#pragma unroll
        for (int mi = 0; mi < 2; mi++) {
            const unsigned short* p0 = sAh + (m0 + mi * 16 + g) * SAS + kb;
            const unsigned short* p1 = p0 + 8 * SAS;
            ah[mi][0] = *(const uint32_t*)p0;
            ah[mi][1] = *(const uint32_t*)p1;
            ah[mi][2] = *(const uint32_t*)(p0 + 8);
            ah[mi][3] = *(const uint32_t*)(p1 + 8);
            const unsigned short* q0 = sAl + (m0 + mi * 16 + g) * SAS + kb;
            const unsigned short* q1 = q0 + 8 * SAS;
            al[mi][0] = *(const uint32_t*)q0;
            al[mi][1] = *(const uint32_t*)q1;
            al[mi][2] = *(const uint32_t*)(q0 + 8);
            al[mi][3] = *(const uint32_t*)(q1 + 8);
        }
        const int kt = kt0 + kti;
#pragma unroll
        for (int ni = 0; ni < 4; ni++) {
            const int nt = wn * 4 + ni;
            uint2 bh = Bf[(nt * KTtot + kt) * 32 + lane];
            uint2 bl = Bf[((16 + nt) * KTtot + kt) * 32 + lane];
            uint32_t bhr[2] = {bh.x, bh.y};
            uint32_t blr[2] = {bl.x, bl.y};
            mma16816(acc[0][ni], ah[0], bhr);
            mma16816(acc[1][ni], ah[1], bhr);
            mma16816(acc[0][ni], al[0], bhr);
            mma16816(acc[1][ni], al[1], bhr);
            mma16816(acc[0][ni], ah[0], blr);
            mma16816(acc[1][ni], ah[1], blr);
        }
    }
}

// ---------------- precompute: P1 = h@We1_top, P2 = h@We1_bot --------------
__global__ __launch_bounds__(256, 2) void precompute_p(const float* __restrict__ h)
{
    extern __shared__ __align__(16) char smem[];
    unsigned short* sAh = (unsigned short*)smem;            // [64][SAS]
    unsigned short* sAl = (unsigned short*)(smem + 17408);

    const int t    = threadIdx.x;
    const int lane = t & 31;
    const int wid  = t >> 5;
    const int wm   = wid >> 2;
    const int wn   = wid & 3;
    const int g    = lane >> 2;
    const int tig  = lane & 3;
    const int n0   = blockIdx.x * 64;

    // gather h rows (coalesced) + bf16 split
    for (int i = t; i < 64 * 32; i += 256) {
        int e = i >> 5;
        int k = (i & 31) * 4;
        int n = n0 + e;
        float4 v = make_float4(0.f, 0.f, 0.f, 0.f);
        if (n < NN) v = *(const float4*)(h + (size_t)n * 128 + k);
        uint32_t h0, l0, h1, l1;
        split_pack(v.x, v.y, h0, l0);
        split_pack(v.z, v.w, h1, l1);
        *(uint2*)(sAh + e * SAS + k) = make_uint2(h0, h1);
        *(uint2*)(sAl + e * SAS + k) = make_uint2(l0, l1);
    }
    __syncthreads();

    float acc[2][4][4];
#pragma unroll
    for (int p = 0; p < 2; p++) {
#pragma unroll
        for (int a = 0; a < 2; a++)
#pragma unroll
            for (int b = 0; b < 4; b++)
#pragma unroll
                for (int c = 0; c < 4; c++) acc[a][b][c] = 0.0f;
        gemm_tiles(sAh, sAl, g_We1f, 16, p * 8, 8, wm, wn, lane, acc);
        float* out = p ? g_P2 : g_P1;
#pragma unroll
        for (int mi = 0; mi < 2; mi++) {
            int rA = n0 + wm * 32 + mi * 16 + g;
            int rB = rA + 8;
#pragma unroll
            for (int ni = 0; ni < 4; ni++) {
                int cb = wn * 32 + ni * 8 + tig * 2;
                if (rA < NN) {
                    out[(size_t)rA * 128 + cb]     = acc[mi][ni][0];
                    out[(size_t)rA * 128 + cb + 1] = acc[mi][ni][1];
                }
                if (rB < NN) {
                    out[(size_t)rB * 128 + cb]     = acc[mi][ni][2];
                    out[(size_t)rB * 128 + cb + 1] = acc[mi][ni][3];
                }
            }
        }
    }
}

// ---------------- edge kernel: 64 edges/CTA, GEMM2+GEMM3 only ------------
#define OFF_AH 0u          // 17408
#define OFF_AL 17408u      // 17408
#define OFF_M  34816u      // 33024
#define OFF_X  67840u
#define SMEM_EDGE_TOTAL 72192

__global__ __launch_bounds__(256, 2) void edge_kernel_mma(
    const float* __restrict__ coord_diff,
    const int* __restrict__ row, const int* __restrict__ col,
    const float* __restrict__ We1, const float* __restrict__ be1,
    const float* __restrict__ be2,
    const float* __restrict__ bc1, const float* __restrict__ Wc2)
{
    extern __shared__ __align__(16) char smem[];
    unsigned short* sAh = (unsigned short*)(smem + OFF_AH);
    unsigned short* sAl = (unsigned short*)(smem + OFF_AL);
    float* sM    = (float*)(smem + OFF_M);
    int*   sRow  = (int*)  (smem + OFF_X);          // 256
    int*   sCol  = (int*)  (smem + OFF_X + 256);    // 256
    float* sRad  = (float*)(smem + OFF_X + 512);    // 256
    float* sCD   = (float*)(smem + OFF_X + 768);    // 768
    float* sBe1  = (float*)(smem + OFF_X + 1536);   // 512
    float* sW256 = (float*)(smem + OFF_X + 2048);   // 512
    float* sBe2  = (float*)(smem + OFF_X + 2560);   // 512
    float* sBc1  = (float*)(smem + OFF_X + 3072);   // 512
    float* sWc2  = (float*)(smem + OFF_X + 3584);   // 512
    float* sCoef = (float*)(smem + OFF_X + 4096);   // 256

    const int t    = threadIdx.x;
    const int lane = t & 31;
    const int wid  = t >> 5;
    const int wm   = wid >> 2;
    const int wn   = wid & 3;
    const int g    = lane >> 2;
    const int tig  = lane & 3;
    const int e0   = blockIdx.x * 64;

    if (t < 64) {
        int e = e0 + t;
        sRow[t] = row[e];
        sCol[t] = col[e];
        float cx = coord_diff[e * 3 + 0];
        float cy = coord_diff[e * 3 + 1];
        float cz = coord_diff[e * 3 + 2];
        sCD[t * 3 + 0] = cx; sCD[t * 3 + 1] = cy; sCD[t * 3 + 2] = cz;
        sRad[t] = cx * cx + cy * cy + cz * cz;
        sCoef[t] = 0.0f;
    }
    if (t < 128) {
        sBe1[t]  = be1[t];
        sW256[t] = We1[256 * 128 + t];
        sBe2[t]  = be2[t];
        sBc1[t]  = bc1[t];
        sWc2[t]  = Wc2[t];
    }
    __syncthreads();

    // ---- h1 = silu(P1[row] + P2[col] + rad*w256 + be1) -> A (K=128) ----
    for (int i = t; i < 64 * 32; i += 256) {
        int e = i >> 5;                 // one edge per warp per iter
        int k = (i & 31) * 4;
        float rad = sRad[e];
        float4 a = *(const float4*)(g_P1 + (size_t)sRow[e] * 128 + k);
        float4 b = *(const float4*)(g_P2 + (size_t)sCol[e] * 128 + k);
        float4 w = *(const float4*)(sW256 + k);
        float4 bb = *(const float4*)(sBe1 + k);
        float x0 = silu_f(a.x + b.x + rad * w.x + bb.x);
        float x1 = silu_f(a.y + b.y + rad * w.y + bb.y);
        float x2 = silu_f(a.z + b.z + rad * w.z + bb.z);
        float x3 = silu_f(a.w + b.w + rad * w.w + bb.w);
        uint32_t h0, l0, h1, l1;
        split_pack(x0, x1, h0, l0);
        split_pack(x2, x3, h1, l1);
        *(uint2*)(sAh + e * SAS + k) = make_uint2(h0, h1);
        *(uint2*)(sAl + e * SAS + k) = make_uint2(l0, l1);
    }
    __syncthreads();

    float acc[2][4][4];

    // ---- GEMM2: m = silu(h1 @ We2 + be2), K=128 ----
#pragma unroll
    for (int a = 0; a < 2; a++)
#pragma unroll
        for (int b = 0; b < 4; b++)
#pragma unroll
            for (int c = 0; c < 4; c++) acc[a][b][c] = 0.0f;
    gemm_tiles(sAh, sAl, g_We2f, 8, 0, 8, wm, wn, lane, acc);
    __syncthreads();

#pragma unroll
    for (int mi = 0; mi < 2; mi++) {
        int rA = wm * 32 + mi * 16 + g;
        int rB = rA + 8;
#pragma unroll
        for (int ni = 0; ni < 4; ni++) {
            int cb = wn * 32 + ni * 8 + tig * 2;
            float b0 = sBe2[cb], b1 = sBe2[cb + 1];
            float m0 = silu_f(acc[mi][ni][0] + b0);
            float m1 = silu_f(acc[mi][ni][1] + b1);
            float m2 = silu_f(acc[mi][ni][2] + b0);
            float m3 = silu_f(acc[mi][ni][3] + b1);
            sM[rA * SMS + cb] = m0;  sM[rA * SMS + cb + 1] = m1;
            sM[rB * SMS + cb] = m2;  sM[rB * SMS + cb + 1] = m3;
            uint32_t hi, lo;
            split_pack(m0, m1, hi, lo);
            *(uint32_t*)(sAh + rA * SAS + cb) = hi;
            *(uint32_t*)(sAl + rA * SAS + cb) = lo;
            split_pack(m2, m3, hi, lo);
            *(uint32_t*)(sAh + rB * SAS + cb) = hi;
            *(uint32_t*)(sAl + rB * SAS + cb) = lo;
        }
    }
    __syncthreads();

    // ---- GEMM3: K=128 ----
#pragma unroll
    for (int a = 0; a < 2; a++)
#pragma unroll
        for (int b = 0; b < 4; b++)
#pragma unroll
            for (int c = 0; c < 4; c++) acc[a][b][c] = 0.0f;
    gemm_tiles(sAh, sAl, g_Wc1f, 8, 0, 8, wm, wn, lane, acc);

    // ---- epilogue3: coef = sum_n silu(D + bc1) * Wc2 ----
    {
        float p[4] = {0.f, 0.f, 0.f, 0.f};
#pragma unroll
        for (int ni = 0; ni < 4; ni++) {
            int cb = wn * 32 + ni * 8 + tig * 2;
            float b0 = sBc1[cb], b1 = sBc1[cb + 1];
            float w0 = sWc2[cb], w1 = sWc2[cb + 1];
#pragma unroll
            for (int mi = 0; mi < 2; mi++) {
                p[mi * 2 + 0] += silu_f(acc[mi][ni][0] + b0) * w0
                               + silu_f(acc[mi][ni][1] + b1) * w1;
                p[mi * 2 + 1] += silu_f(acc[mi][ni][2] + b0) * w0
                               + silu_f(acc[mi][ni][3] + b1) * w1;
            }
        }
#pragma unroll
        for (int j = 0; j < 4; j++) {
            p[j] += __shfl_xor_sync(0xffffffffu, p[j], 1);
            p[j] += __shfl_xor_sync(0xffffffffu, p[j], 2);
        }
        if (tig == 0) {
#pragma unroll
            for (int j = 0; j < 4; j++) {
                int rr = wm * 32 + (j >> 1) * 16 + (j & 1) * 8 + g;
                atomicAdd(&sCoef[rr], p[j]);
            }
        }
    }
    __syncthreads();

    // ---- force scatter ----
    if (t < 64) {
        int r = sRow[t];
        float c = sCoef[t];
#pragma unroll
        for (int q = 0; q < 3; q++) {
            float v = sCD[t * 3 + q] * c;
            v = fminf(fmaxf(v, -100.0f), 100.0f);
            atomicAdd(&g_fsum[r * 3 + q], v);
        }
        atomicAdd(&g_cnt[r], 1.0f);
    }
    // ---- agg scatter (coalesced over d within warp) ----
    for (int i = t; i < 64 * 128; i += 256) {
        int e = i >> 7;
        int dd = i & 127;
        atomicAdd(&g_agg[(size_t)sRow[e] * 128 + dd], sM[e * SMS + dd]);
    }
}

// ---------------------------------------------------------------------------
// Node kernel (proven scalar version)
// out layout: [vel (N)] [force (N*3)] [h_out (N*128)]
// ---------------------------------------------------------------------------
__global__ __launch_bounds__(256, 3) void node_kernel(
    const float* __restrict__ h,
    const float* __restrict__ Wn1, const float* __restrict__ bn1,
    const float* __restrict__ Wn2, const float* __restrict__ bn2,
    const float* __restrict__ Wv1, const float* __restrict__ bv1,
    const float* __restrict__ Wv2, const float* __restrict__ bv2,
    float* __restrict__ out)
{
    extern __shared__ float sm[];
    float* sB   = sm;            // 4096
    float* sA   = sB + 4096;     // 2112
    float* sH   = sA + 2112;     // 8448
    float* sVel = sH + 8448;     // 64

    const int t    = threadIdx.x;
    const int lane = t & 31;
    const int warp = t >> 5;
    const int col0 = lane * 4;
    const int row0 = warp * 8;
    const int n0   = blockIdx.x * 64;

    float acc[8][4];

#pragma unroll
    for (int i = 0; i < 8; i++)
#pragma unroll
        for (int j = 0; j < 4; j++) acc[i][j] = bn1[col0 + j];

    for (int kc = 0; kc < 8; kc++) {
        __syncthreads();
        const float4* Wsrc = (const float4*)(Wn1 + kc * 32 * 128);
        float4* Bdst = (float4*)sB;
        Bdst[t]       = Wsrc[t];
        Bdst[t + 256] = Wsrc[t + 256];
        Bdst[t + 512] = Wsrc[t + 512];
        Bdst[t + 768] = Wsrc[t + 768];
#pragma unroll
        for (int it = 0; it < 2; it++) {
            int i  = t + it * 256;
            int e  = i >> 3;
            int kq = i & 7;
            int n  = n0 + e;
            float4 v = make_float4(0.f, 0.f, 0.f, 0.f);
            if (n < NN) {
                int k = kc * 32 + kq * 4;
                const float* src = (k < 128)
                    ? (h + (size_t)n * 128 + k)
                    : (g_agg + (size_t)n * 128 + (k - 128));
                v = *(const float4*)src;
            }
            float* dst = sA + e * 33 + kq * 4;
            dst[0] = v.x; dst[1] = v.y; dst[2] = v.z; dst[3] = v.w;
        }
        __syncthreads();
#pragma unroll
        for (int kk = 0; kk < 32; kk++) {
            float4 bv = *(const float4*)(sB + kk * 128 + col0);
#pragma unroll
            for (int i = 0; i < 8; i++) {
                float a = sA[(row0 + i) * 33 + kk];
                acc[i][0] += a * bv.x;
                acc[i][1] += a * bv.y;
                acc[i][2] += a * bv.z;
                acc[i][3] += a * bv.w;
            }
        }
    }
#pragma unroll
    for (int i = 0; i < 8; i++) {
        float4 v;
        v.x = silu_f(acc[i][0]); v.y = silu_f(acc[i][1]);
        v.z = silu_f(acc[i][2]); v.w = silu_f(acc[i][3]);
        *(float4*)(sH + (row0 + i) * 132 + col0) = v;
    }

#pragma unroll
    for (int i = 0; i < 8; i++)
#pragma unroll
        for (int j = 0; j < 4; j++) acc[i][j] = bn2[col0 + j];

    for (int kc = 0; kc < 4; kc++) {
        __syncthreads();
        const float4* Wsrc = (const float4*)(Wn2 + kc * 32 * 128);
        float4* Bdst = (float4*)sB;
        Bdst[t]       = Wsrc[t];
        Bdst[t + 256] = Wsrc[t + 256];
        Bdst[t + 512] = Wsrc[t + 512];
        Bdst[t + 768] = Wsrc[t + 768];
        __syncthreads();
#pragma unroll
        for (int kk = 0; kk < 32; kk++) {
            float4 bv = *(const float4*)(sB + kk * 128 + col0);
            int kg = kc * 32 + kk;
#pragma unroll
            for (int i = 0; i < 8; i++) {
                float a = sH[(row0 + i) * 132 + kg];
                acc[i][0] += a * bv.x;
                acc[i][1] += a * bv.y;
                acc[i][2] += a * bv.z;
                acc[i][3] += a * bv.w;
            }
        }
    }
    {
        float* outH = out + (size_t)4 * NN;
#pragma unroll
        for (int i = 0; i < 8; i++) {
            int n = n0 + row0 + i;
            if (n < NN) {
                float4 v;
                v.x = acc[i][0]; v.y = acc[i][1]; v.z = acc[i][2]; v.w = acc[i][3];
                *(float4*)(outH + (size_t)n * 128 + col0) = v;
            }
        }
    }

#pragma unroll
    for (int i = 0; i < 8; i++)
#pragma unroll
        for (int j = 0; j < 4; j++) acc[i][j] = bv1[col0 + j];

    for (int kc = 0; kc < 4; kc++) {
        __syncthreads();
        const float4* Wsrc = (const float4*)(Wv1 + kc * 32 * 128);
        float4* Bdst = (float4*)sB;
        Bdst[t]       = Wsrc[t];
        Bdst[t + 256] = Wsrc[t + 256];
        Bdst[t + 512] = Wsrc[t + 512];
        Bdst[t + 768] = Wsrc[t + 768];
#pragma unroll
        for (int it = 0; it < 2; it++) {
            int i  = t + it * 256;
            int e  = i >> 3;
            int kq = i & 7;
            int n  = n0 + e;
            float4 v = make_float4(0.f, 0.f, 0.f, 0.f);
            if (n < NN) {
                int k = kc * 32 + kq * 4;
                v = *(const float4*)(h + (size_t)n * 128 + k);
            }
            float* dst = sA + e * 33 + kq * 4;
            dst[0] = v.x; dst[1] = v.y; dst[2] = v.z; dst[3] = v.w;
        }
        __syncthreads();
#pragma unroll
        for (int kk = 0; kk < 32; kk++) {
            float4 bv = *(const float4*)(sB + kk * 128 + col0);
#pragma unroll
            for (int i = 0; i < 8; i++) {
                float a = sA[(row0 + i) * 33 + kk];
                acc[i][0] += a * bv.x;
                acc[i][1] += a * bv.y;
                acc[i][2] += a * bv.z;
                acc[i][3] += a * bv.w;
            }
        }
    }
    {
        float wv[4];
#pragma unroll
        for (int j = 0; j < 4; j++) wv[j] = Wv2[col0 + j];
#pragma unroll
        for (int i = 0; i < 8; i++) {
            float v = silu_f(acc[i][0]) * wv[0] + silu_f(acc[i][1]) * wv[1]
                    + silu_f(acc[i][2]) * wv[2] + silu_f(acc[i][3]) * wv[3];
#pragma unroll
            for (int o = 16; o > 0; o >>= 1) v += __shfl_xor_sync(0xffffffffu, v, o);
            if (lane == 0) sVel[row0 + i] = v;
        }
    }
    __syncthreads();

    if (t < 64) {
        int n = n0 + t;
        if (n < NN) {
            out[n] = sVel[t] + bv2[0];
            float c = g_cnt[n];
            float inv = 1.0f / fmaxf(c, 1.0f);
            out[NN + (size_t)n * 3 + 0] = g_fsum[n * 3 + 0] * inv;
            out[NN + (size_t)n * 3 + 1] = g_fsum[n * 3 + 1] * inv;
            out[NN + (size_t)n * 3 + 2] = g_fsum[n * 3 + 2] * inv;
        }
    }
}

// ---------------------------------------------------------------------------
extern "C" void kernel_launch(void* const* d_in, const int* in_sizes, int n_in,
                              void* d_out, int out_size)
{
    const float* h          = (const float*)d_in[0];
    const float* coord_diff = (const float*)d_in[1];
    const int*   row        = (const int*)  d_in[2];
    const int*   col        = (const int*)  d_in[3];
    const float* We1 = (const float*)d_in[4];
    const float* be1 = (const float*)d_in[5];
    const float* We2 = (const float*)d_in[6];
    const float* be2 = (const float*)d_in[7];
    const float* Wn1 = (const float*)d_in[8];
    const float* bn1 = (const float*)d_in[9];
    const float* Wn2 = (const float*)d_in[10];
    const float* bn2 = (const float*)d_in[11];
    const float* Wc1 = (const float*)d_in[12];
    const float* bc1 = (const float*)d_in[13];
    const float* Wc2 = (const float*)d_in[14];
    const float* Wv1 = (const float*)d_in[15];
    const float* bv1 = (const float*)d_in[16];
    const float* Wv2 = (const float*)d_in[17];
    const float* bv2 = (const float*)d_in[18];
    float* out = (float*)d_out;

    void *aggp, *fsump, *cntp;
    cudaGetSymbolAddress(&aggp, g_agg);
    cudaGetSymbolAddress(&fsump, g_fsum);
    cudaGetSymbolAddress(&cntp, g_cnt);
    cudaMemsetAsync(aggp,  0, (size_t)NN * 128 * sizeof(float));
    cudaMemsetAsync(fsump, 0, (size_t)NN * 3 * sizeof(float));
    cudaMemsetAsync(cntp,  0, (size_t)NN * sizeof(float));

    prep_weights_f<<<256, 256>>>(We1, We2, Wc1);

    precompute_p<<<(NN + 63) / 64, 256, 34816>>>(h);

    cudaFuncSetAttribute(edge_kernel_mma, cudaFuncAttributeMaxDynamicSharedMemorySize,
                         SMEM_EDGE_TOTAL);
    edge_kernel_mma<<<EE / 64, 256, SMEM_EDGE_TOTAL>>>(
        coord_diff, row, col, We1, be1, be2, bc1, Wc2);

    const size_t smN = (size_t)(4096 + 2112 + 8448 + 64) * sizeof(float);
    cudaFuncSetAttribute(node_kernel, cudaFuncAttributeMaxDynamicSharedMemorySize, (int)smN);
    node_kernel<<<(NN + 63) / 64, 256, smN>>>(h, Wn1, bn1, Wn2, bn2,
                                              Wv1, bv1, Wv2, bv2, out);
}

// round 8
// speedup vs baseline: 4.3132x; 1.0525x over previous
#include <cuda_runtime.h>
#include <cuda_bf16.h>
#include <cstdint>

#define NN 50000
#define EE 800000

// ---------------- scratch (__device__ globals; no allocs) ----------------
__device__ float g_agg[(size_t)NN * 128];
__device__ float g_fsum[NN * 3];
__device__ float g_cnt[NN];
__device__ float g_P1[(size_t)NN * 128];   // h @ We1[0:128,:]
__device__ float g_P2[(size_t)NN * 128];   // h @ We1[128:256,:]
__device__ float g_Q1[(size_t)NN * 128];   // h @ Wn1[0:128,:] + bn1

// Weight fragments for mma.sync m16n8k16 (bf16 hi/lo), per-lane order:
//   u32 index = ((hl*16 + nt)*KT + kt)*64 + lane*2 + r
__device__ __align__(16) uint2 g_We1f[16384];  // K=256
__device__ __align__(16) uint2 g_We2f[8192];   // K=128
__device__ __align__(16) uint2 g_Wc1f[8192];   // K=128
__device__ __align__(16) uint2 g_Wn1tf[8192];  // Wn1 top half, K=128
__device__ __align__(16) uint2 g_Wv1f[8192];   // Wv1, K=128

__device__ __forceinline__ float silu_f(float x) {
    return x / (1.0f + __expf(-x));
}

__device__ __forceinline__ void split_pack(float f0, float f1, uint32_t& hi, uint32_t& lo) {
    __nv_bfloat162 bh = __floats2bfloat162_rn(f0, f1);
    float2 bf = __bfloat1622float2(bh);
    __nv_bfloat162 bl = __floats2bfloat162_rn(f0 - bf.x, f1 - bf.y);
    hi = *(uint32_t*)&bh;
    lo = *(uint32_t*)&bl;
}

__device__ __forceinline__ void mma16816(float* c, const uint32_t* a, const uint32_t* b) {
    asm volatile(
        "mma.sync.aligned.m16n8k16.row.col.f32.bf16.bf16.f32 "
        "{%0,%1,%2,%3}, {%4,%5,%6,%7}, {%8,%9}, {%0,%1,%2,%3};"
        : "+f"(c[0]), "+f"(c[1]), "+f"(c[2]), "+f"(c[3])
        : "r"(a[0]), "r"(a[1]), "r"(a[2]), "r"(a[3]), "r"(b[0]), "r"(b[1]));
}

__device__ __forceinline__ void red_add_v4(float* gptr, float4 v) {
    asm volatile("red.global.add.v4.f32 [%0], {%1, %2, %3, %4};"
                 :: "l"(gptr), "f"(v.x), "f"(v.y), "f"(v.z), "f"(v.w) : "memory");
}

#define SAS 136   // A stride (bf16) for K=128 tiles
#define SMS 132   // fp32 m stride (floats), 16B-aligned rows

// ---------------- prep: weights -> bf16 hi/lo fragment order --------------
__global__ void prep_weights_f(const float* __restrict__ We1,
                               const float* __restrict__ We2,
                               const float* __restrict__ Wc1,
                               const float* __restrict__ Wn1,
                               const float* __restrict__ Wv1) {
    int i = blockIdx.x * blockDim.x + threadIdx.x;
    const float* W; uint32_t* out; int KT, j;
    if (i < 32768)      { W = We1;       out = (uint32_t*)g_We1f;  KT = 16; j = i; }
    else if (i < 49152) { W = We2;       out = (uint32_t*)g_We2f;  KT = 8;  j = i - 32768; }
    else if (i < 65536) { W = Wc1;       out = (uint32_t*)g_Wc1f;  KT = 8;  j = i - 49152; }
    else if (i < 81920) { W = Wn1;       out = (uint32_t*)g_Wn1tf; KT = 8;  j = i - 65536; }
    else if (i < 98304) { W = Wv1;       out = (uint32_t*)g_Wv1f;  KT = 8;  j = i - 81920; }
    else return;
    int per_hl = 16 * KT * 64;
    int hl = j / per_hl; int rem = j % per_hl;
    int nt = rem / (KT * 64); rem %= KT * 64;
    int kt = rem / 64; rem %= 64;
    int lane = rem >> 1, r = rem & 1;
    int g = lane >> 2, tig = lane & 3;
    int n = nt * 8 + g;
    int k = kt * 16 + tig * 2 + r * 8;
    float w0 = W[k * 128 + n], w1 = W[(k + 1) * 128 + n];
    __nv_bfloat162 p;
    if (hl == 0) {
        p.x = __float2bfloat16(w0);
        p.y = __float2bfloat16(w1);
    } else {
        __nv_bfloat16 h0 = __float2bfloat16(w0), h1 = __float2bfloat16(w1);
        p.x = __float2bfloat16(w0 - __bfloat162float(h0));
        p.y = __float2bfloat16(w1 - __bfloat162float(h1));
    }
    out[((hl * 16 + nt) * KT + kt) * 64 + lane * 2 + r] = *(uint32_t*)&p;
}

// ---------------- shared GEMM core: 2x4 mma tiles per warp ----------------
__device__ __forceinline__ void gemm_tiles(
    const unsigned short* __restrict__ sAh, const unsigned short* __restrict__ sAl,
    const uint2* __restrict__ Bf, int KTtot, int kt0, int ktn,
    int wm, int wn, int lane, float acc[2][4][4])
{
    const int g = lane >> 2, tig = lane & 3;
    const int m0 = wm * 32;
    for (int kti = 0; kti < ktn; kti++) {
        uint32_t ah[2][4], al[2][4];
        const int kb = kti * 16 + tig * 2;
#pragma unroll
        for (int mi = 0; mi < 2; mi++) {
            const unsigned short* p0 = sAh + (m0 + mi * 16 + g) * SAS + kb;
            const unsigned short* p1 = p0 + 8 * SAS;
            ah[mi][0] = *(const uint32_t*)p0;
            ah[mi][1] = *(const uint32_t*)p1;
            ah[mi][2] = *(const uint32_t*)(p0 + 8);
            ah[mi][3] = *(const uint32_t*)(p1 + 8);
            const unsigned short* q0 = sAl + (m0 + mi * 16 + g) * SAS + kb;
            const unsigned short* q1 = q0 + 8 * SAS;
            al[mi][0] = *(const uint32_t*)q0;
            al[mi][1] = *(const uint32_t*)q1;
            al[mi][2] = *(const uint32_t*)(q0 + 8);
            al[mi][3] = *(const uint32_t*)(q1 + 8);
        }
        const int kt = kt0 + kti;
#pragma unroll
        for (int ni = 0; ni < 4; ni++) {
            const int nt = wn * 4 + ni;
            uint2 bh = Bf[(nt * KTtot + kt) * 32 + lane];
            uint2 bl = Bf[((16 + nt) * KTtot + kt) * 32 + lane];
            uint32_t bhr[2] = {bh.x, bh.y};
            uint32_t blr[2] = {bl.x, bl.y};
            mma16816(acc[0][ni], ah[0], bhr);
            mma16816(acc[1][ni], ah[1], bhr);
            mma16816(acc[0][ni], al[0], bhr);
            mma16816(acc[1][ni], al[1], bhr);
            mma16816(acc[0][ni], ah[0], blr);
            mma16816(acc[1][ni], ah[1], blr);
        }
    }
}

// ---------------- precompute: P1, P2, Q1, vel — all h-only GEMMs ----------
// smem: sAh [0,17408), sAl [17408,34816), bn1 34816, bv1 35328, Wv2 35840,
//       sVel 36352 ; total 36608 -> launch 36864
__global__ __launch_bounds__(256, 2) void precompute_p(
    const float* __restrict__ h,
    const float* __restrict__ bn1,
    const float* __restrict__ bv1,
    const float* __restrict__ Wv2, const float* __restrict__ bv2,
    float* __restrict__ out)
{
    extern __shared__ __align__(16) char smem[];
    unsigned short* sAh = (unsigned short*)smem;
    unsigned short* sAl = (unsigned short*)(smem + 17408);
    float* sBn1 = (float*)(smem + 34816);
    float* sBv1 = (float*)(smem + 35328);
    float* sWv2 = (float*)(smem + 35840);
    float* sVel = (float*)(smem + 36352);

    const int t    = threadIdx.x;
    const int lane = t & 31;
    const int wid  = t >> 5;
    const int wm   = wid >> 2;
    const int wn   = wid & 3;
    const int g    = lane >> 2;
    const int tig  = lane & 3;
    const int n0   = blockIdx.x * 64;

    if (t < 128) {
        sBn1[t] = bn1[t];
        sBv1[t] = bv1[t];
        sWv2[t] = Wv2[t];
    }
    if (t < 64) sVel[t] = 0.0f;

    for (int i = t; i < 64 * 32; i += 256) {
        int e = i >> 5;
        int k = (i & 31) * 4;
        int n = n0 + e;
        float4 v = make_float4(0.f, 0.f, 0.f, 0.f);
        if (n < NN) v = *(const float4*)(h + (size_t)n * 128 + k);
        uint32_t h0, l0, h1, l1;
        split_pack(v.x, v.y, h0, l0);
        split_pack(v.z, v.w, h1, l1);
        *(uint2*)(sAh + e * SAS + k) = make_uint2(h0, h1);
        *(uint2*)(sAl + e * SAS + k) = make_uint2(l0, l1);
    }
    __syncthreads();

    float acc[2][4][4];

    // ---- P1, P2 (We1 halves) ----
#pragma unroll
    for (int p = 0; p < 2; p++) {
#pragma unroll
        for (int a = 0; a < 2; a++)
#pragma unroll
            for (int b = 0; b < 4; b++)
#pragma unroll
                for (int c = 0; c < 4; c++) acc[a][b][c] = 0.0f;
        gemm_tiles(sAh, sAl, g_We1f, 16, p * 8, 8, wm, wn, lane, acc);
        float* outp = p ? g_P2 : g_P1;
#pragma unroll
        for (int mi = 0; mi < 2; mi++) {
            int rA = n0 + wm * 32 + mi * 16 + g;
            int rB = rA + 8;
#pragma unroll
            for (int ni = 0; ni < 4; ni++) {
                int cb = wn * 32 + ni * 8 + tig * 2;
                if (rA < NN) {
                    outp[(size_t)rA * 128 + cb]     = acc[mi][ni][0];
                    outp[(size_t)rA * 128 + cb + 1] = acc[mi][ni][1];
                }
                if (rB < NN) {
                    outp[(size_t)rB * 128 + cb]     = acc[mi][ni][2];
                    outp[(size_t)rB * 128 + cb + 1] = acc[mi][ni][3];
                }
            }
        }
    }

    // ---- Q1 = h @ Wn1_top + bn1 ----
    {
#pragma unroll
        for (int a = 0; a < 2; a++)
#pragma unroll
            for (int b = 0; b < 4; b++)
#pragma unroll
                for (int c = 0; c < 4; c++) acc[a][b][c] = 0.0f;
        gemm_tiles(sAh, sAl, g_Wn1tf, 8, 0, 8, wm, wn, lane, acc);
#pragma unroll
        for (int mi = 0; mi < 2; mi++) {
            int rA = n0 + wm * 32 + mi * 16 + g;
            int rB = rA + 8;
#pragma unroll
            for (int ni = 0; ni < 4; ni++) {
                int cb = wn * 32 + ni * 8 + tig * 2;
                float b0 = sBn1[cb], b1 = sBn1[cb + 1];
                if (rA < NN) {
                    g_Q1[(size_t)rA * 128 + cb]     = acc[mi][ni][0] + b0;
                    g_Q1[(size_t)rA * 128 + cb + 1] = acc[mi][ni][1] + b1;
                }
                if (rB < NN) {
                    g_Q1[(size_t)rB * 128 + cb]     = acc[mi][ni][2] + b0;
                    g_Q1[(size_t)rB * 128 + cb + 1] = acc[mi][ni][3] + b1;
                }
            }
        }
    }

    // ---- vel = silu(h @ Wv1 + bv1) @ Wv2 + bv2 -> out[0..NN) ----
    {
#pragma unroll
        for (int a = 0; a < 2; a++)
#pragma unroll
            for (int b = 0; b < 4; b++)
#pragma unroll
                for (int c = 0; c < 4; c++) acc[a][b][c] = 0.0f;
        gemm_tiles(sAh, sAl, g_Wv1f, 8, 0, 8, wm, wn, lane, acc);
        float p[4] = {0.f, 0.f, 0.f, 0.f};
#pragma unroll
        for (int ni = 0; ni < 4; ni++) {
            int cb = wn * 32 + ni * 8 + tig * 2;
            float b0 = sBv1[cb], b1 = sBv1[cb + 1];
            float w0 = sWv2[cb], w1 = sWv2[cb + 1];
#pragma unroll
            for (int mi = 0; mi < 2; mi++) {
                p[mi * 2 + 0] += silu_f(acc[mi][ni][0] + b0) * w0
                               + silu_f(acc[mi][ni][1] + b1) * w1;
                p[mi * 2 + 1] += silu_f(acc[mi][ni][2] + b0) * w0
                               + silu_f(acc[mi][ni][3] + b1) * w1;
            }
        }
#pragma unroll
        for (int j = 0; j < 4; j++) {
            p[j] += __shfl_xor_sync(0xffffffffu, p[j], 1);
            p[j] += __shfl_xor_sync(0xffffffffu, p[j], 2);
        }
        __syncthreads();   // sVel zeros visible
        if (tig == 0) {
#pragma unroll
            for (int j = 0; j < 4; j++) {
                int rr = wm * 32 + (j >> 1) * 16 + (j & 1) * 8 + g;
                atomicAdd(&sVel[rr], p[j]);
            }
        }
        __syncthreads();
        if (t < 64) {
            int n = n0 + t;
            if (n < NN) out[n] = sVel[t] + bv2[0];
        }
    }
}

// ---------------- edge kernel: 64 edges/CTA, GEMM2+GEMM3 ------------------
#define OFF_AH 0u          // 17408
#define OFF_AL 17408u      // 17408
#define OFF_M  34816u      // 64*132*4 = 33792
#define OFF_X  68608u
#define SMEM_EDGE_TOTAL 72960

__global__ __launch_bounds__(256, 2) void edge_kernel_mma(
    const float* __restrict__ coord_diff,
    const int* __restrict__ row, const int* __restrict__ col,
    const float* __restrict__ We1, const float* __restrict__ be1,
    const float* __restrict__ be2,
    const float* __restrict__ bc1, const float* __restrict__ Wc2)
{
    extern __shared__ __align__(16) char smem[];
    unsigned short* sAh = (unsigned short*)(smem + OFF_AH);
    unsigned short* sAl = (unsigned short*)(smem + OFF_AL);
    float* sM    = (float*)(smem + OFF_M);
    int*   sRow  = (int*)  (smem + OFF_X);          // 256
    int*   sCol  = (int*)  (smem + OFF_X + 256);    // 256
    float* sRad  = (float*)(smem + OFF_X + 512);    // 256
    float* sCD   = (float*)(smem + OFF_X + 768);    // 768
    float* sBe1  = (float*)(smem + OFF_X + 1536);   // 512
    float* sW256 = (float*)(smem + OFF_X + 2048);   // 512
    float* sBe2  = (float*)(smem + OFF_X + 2560);   // 512
    float* sBc1  = (float*)(smem + OFF_X + 3072);   // 512
    float* sWc2  = (float*)(smem + OFF_X + 3584);   // 512
    float* sCoef = (float*)(smem + OFF_X + 4096);   // 256

    const int t    = threadIdx.x;
    const int lane = t & 31;
    const int wid  = t >> 5;
    const int wm   = wid >> 2;
    const int wn   = wid & 3;
    const int g    = lane >> 2;
    const int tig  = lane & 3;
    const int e0   = blockIdx.x * 64;

    if (t < 64) {
        int e = e0 + t;
        sRow[t] = row[e];
        sCol[t] = col[e];
        float cx = coord_diff[e * 3 + 0];
        float cy = coord_diff[e * 3 + 1];
        float cz = coord_diff[e * 3 + 2];
        sCD[t * 3 + 0] = cx; sCD[t * 3 + 1] = cy; sCD[t * 3 + 2] = cz;
        sRad[t] = cx * cx + cy * cy + cz * cz;
        sCoef[t] = 0.0f;
    }
    if (t < 128) {
        sBe1[t]  = be1[t];
        sW256[t] = We1[256 * 128 + t];
        sBe2[t]  = be2[t];
        sBc1[t]  = bc1[t];
        sWc2[t]  = Wc2[t];
    }
    __syncthreads();

    // ---- h1 = silu(P1[row] + P2[col] + rad*w256 + be1) -> A (K=128) ----
    for (int i = t; i < 64 * 32; i += 256) {
        int e = i >> 5;
        int k = (i & 31) * 4;
        float rad = sRad[e];
        float4 a = *(const float4*)(g_P1 + (size_t)sRow[e] * 128 + k);
        float4 b = *(const float4*)(g_P2 + (size_t)sCol[e] * 128 + k);
        float4 w = *(const float4*)(sW256 + k);
        float4 bb = *(const float4*)(sBe1 + k);
        float x0 = silu_f(a.x + b.x + rad * w.x + bb.x);
        float x1 = silu_f(a.y + b.y + rad * w.y + bb.y);
        float x2 = silu_f(a.z + b.z + rad * w.z + bb.z);
        float x3 = silu_f(a.w + b.w + rad * w.w + bb.w);
        uint32_t h0, l0, h1, l1;
        split_pack(x0, x1, h0, l0);
        split_pack(x2, x3, h1, l1);
        *(uint2*)(sAh + e * SAS + k) = make_uint2(h0, h1);
        *(uint2*)(sAl + e * SAS + k) = make_uint2(l0, l1);
    }
    __syncthreads();

    float acc[2][4][4];

    // ---- GEMM2: m = silu(h1 @ We2 + be2), K=128 ----
#pragma unroll
    for (int a = 0; a < 2; a++)
#pragma unroll
        for (int b = 0; b < 4; b++)
#pragma unroll
            for (int c = 0; c < 4; c++) acc[a][b][c] = 0.0f;
    gemm_tiles(sAh, sAl, g_We2f, 8, 0, 8, wm, wn, lane, acc);
    __syncthreads();

#pragma unroll
    for (int mi = 0; mi < 2; mi++) {
        int rA = wm * 32 + mi * 16 + g;
        int rB = rA + 8;
#pragma unroll
        for (int ni = 0; ni < 4; ni++) {
            int cb = wn * 32 + ni * 8 + tig * 2;
            float b0 = sBe2[cb], b1 = sBe2[cb + 1];
            float m0 = silu_f(acc[mi][ni][0] + b0);
            float m1 = silu_f(acc[mi][ni][1] + b1);
            float m2 = silu_f(acc[mi][ni][2] + b0);
            float m3 = silu_f(acc[mi][ni][3] + b1);
            sM[rA * SMS + cb] = m0;  sM[rA * SMS + cb + 1] = m1;
            sM[rB * SMS + cb] = m2;  sM[rB * SMS + cb + 1] = m3;
            uint32_t hi, lo;
            split_pack(m0, m1, hi, lo);
            *(uint32_t*)(sAh + rA * SAS + cb) = hi;
            *(uint32_t*)(sAl + rA * SAS + cb) = lo;
            split_pack(m2, m3, hi, lo);
            *(uint32_t*)(sAh + rB * SAS + cb) = hi;
            *(uint32_t*)(sAl + rB * SAS + cb) = lo;
        }
    }
    __syncthreads();

    // ---- GEMM3: K=128 ----
#pragma unroll
    for (int a = 0; a < 2; a++)
#pragma unroll
        for (int b = 0; b < 4; b++)
#pragma unroll
            for (int c = 0; c < 4; c++) acc[a][b][c] = 0.0f;
    gemm_tiles(sAh, sAl, g_Wc1f, 8, 0, 8, wm, wn, lane, acc);

    // ---- epilogue3: coef = sum_n silu(D + bc1) * Wc2 ----
    {
        float p[4] = {0.f, 0.f, 0.f, 0.f};
#pragma unroll
        for (int ni = 0; ni < 4; ni++) {
            int cb = wn * 32 + ni * 8 + tig * 2;
            float b0 = sBc1[cb], b1 = sBc1[cb + 1];
            float w0 = sWc2[cb], w1 = sWc2[cb + 1];
#pragma unroll
            for (int mi = 0; mi < 2; mi++) {
                p[mi * 2 + 0] += silu_f(acc[mi][ni][0] + b0) * w0
                               + silu_f(acc[mi][ni][1] + b1) * w1;
                p[mi * 2 + 1] += silu_f(acc[mi][ni][2] + b0) * w0
                               + silu_f(acc[mi][ni][3] + b1) * w1;
            }
        }
#pragma unroll
        for (int j = 0; j < 4; j++) {
            p[j] += __shfl_xor_sync(0xffffffffu, p[j], 1);
            p[j] += __shfl_xor_sync(0xffffffffu, p[j], 2);
        }
        if (tig == 0) {
#pragma unroll
            for (int j = 0; j < 4; j++) {
                int rr = wm * 32 + (j >> 1) * 16 + (j & 1) * 8 + g;
                atomicAdd(&sCoef[rr], p[j]);
            }
        }
    }
    __syncthreads();

    // ---- force scatter ----
    if (t < 64) {
        int r = sRow[t];
        float c = sCoef[t];
#pragma unroll
        for (int q = 0; q < 3; q++) {
            float v = sCD[t * 3 + q] * c;
            v = fminf(fmaxf(v, -100.0f), 100.0f);
            atomicAdd(&g_fsum[r * 3 + q], v);
        }
        atomicAdd(&g_cnt[r], 1.0f);
    }
    // ---- agg scatter: red.v4 (one 16B RED per lane) ----
    for (int i = t; i < 64 * 32; i += 256) {
        int e = i >> 5;
        int dd = (i & 31) * 4;
        float4 v = *(const float4*)(sM + e * SMS + dd);
        red_add_v4(&g_agg[(size_t)sRow[e] * 128 + dd], v);
    }
}

// ---------------------------------------------------------------------------
// Node kernel: h_out = silu(Q1 + agg@Wn1_bot) @ Wn2 + bn2 ; force normalize
// out layout: [vel (N)] [force (N*3)] [h_out (N*128)]
// ---------------------------------------------------------------------------
__global__ __launch_bounds__(256, 3) void node_kernel(
    const float* __restrict__ Wn1, const float* __restrict__ Wn2,
    const float* __restrict__ bn2,
    float* __restrict__ out)
{
    extern __shared__ float sm[];
    float* sB   = sm;            // 4096
    float* sA   = sB + 4096;     // 2112
    float* sH   = sA + 2112;     // 8448

    const int t    = threadIdx.x;
    const int lane = t & 31;
    const int warp = t >> 5;
    const int col0 = lane * 4;
    const int row0 = warp * 8;
    const int n0   = blockIdx.x * 64;

    float acc[8][4];

    // ---- GEMM1: acc = Q1 + agg @ Wn1_bot (K=128) ----
#pragma unroll
    for (int i = 0; i < 8; i++) {
        int n = n0 + row0 + i;
        if (n < NN) {
            float4 q = *(const float4*)(g_Q1 + (size_t)n * 128 + col0);
            acc[i][0] = q.x; acc[i][1] = q.y; acc[i][2] = q.z; acc[i][3] = q.w;
        } else {
            acc[i][0] = acc[i][1] = acc[i][2] = acc[i][3] = 0.0f;
        }
    }

    for (int kc = 0; kc < 4; kc++) {
        __syncthreads();
        const float4* Wsrc = (const float4*)(Wn1 + (128 + kc * 32) * 128);
        float4* Bdst = (float4*)sB;
        Bdst[t]       = Wsrc[t];
        Bdst[t + 256] = Wsrc[t + 256];
        Bdst[t + 512] = Wsrc[t + 512];
        Bdst[t + 768] = Wsrc[t + 768];
        {
            int i  = t;
            int e  = i >> 2;           // 64 rows x 4 quads
            int kq = i & 3;
            int n  = n0 + e;
            float4 v = make_float4(0.f, 0.f, 0.f, 0.f);
            if (n < NN) {
                int k = kc * 32 + kq * 8;
                v = *(const float4*)(g_agg + (size_t)n * 128 + k);
                float4 v2 = *(const float4*)(g_agg + (size_t)n * 128 + k + 4);
                float* dst = sA + e * 33 + kq * 8;
                dst[0] = v.x; dst[1] = v.y; dst[2] = v.z; dst[3] = v.w;
                dst[4] = v2.x; dst[5] = v2.y; dst[6] = v2.z; dst[7] = v2.w;
            } else {
                float* dst = sA + e * 33 + kq * 8;
#pragma unroll
                for (int q = 0; q < 8; q++) dst[q] = 0.0f;
            }
        }
        __syncthreads();
#pragma unroll
        for (int kk = 0; kk < 32; kk++) {
            float4 bv = *(const float4*)(sB + kk * 128 + col0);
#pragma unroll
            for (int i = 0; i < 8; i++) {
                float a = sA[(row0 + i) * 33 + kk];
                acc[i][0] += a * bv.x;
                acc[i][1] += a * bv.y;
                acc[i][2] += a * bv.z;
                acc[i][3] += a * bv.w;
            }
        }
    }
#pragma unroll
    for (int i = 0; i < 8; i++) {
        float4 v;
        v.x = silu_f(acc[i][0]); v.y = silu_f(acc[i][1]);
        v.z = silu_f(acc[i][2]); v.w = silu_f(acc[i][3]);
        *(float4*)(sH + (row0 + i) * 132 + col0) = v;
    }

    // ---- GEMM2: h_out = sH @ Wn2 + bn2 ----
#pragma unroll
    for (int i = 0; i < 8; i++)
#pragma unroll
        for (int j = 0; j < 4; j++) acc[i][j] = bn2[col0 + j];

    for (int kc = 0; kc < 4; kc++) {
        __syncthreads();
        const float4* Wsrc = (const float4*)(Wn2 + kc * 32 * 128);
        float4* Bdst = (float4*)sB;
        Bdst[t]       = Wsrc[t];
        Bdst[t + 256] = Wsrc[t + 256];
        Bdst[t + 512] = Wsrc[t + 512];
        Bdst[t + 768] = Wsrc[t + 768];
        __syncthreads();
#pragma unroll
        for (int kk = 0; kk < 32; kk++) {
            float4 bv = *(const float4*)(sB + kk * 128 + col0);
            int kg = kc * 32 + kk;
#pragma unroll
            for (int i = 0; i < 8; i++) {
                float a = sH[(row0 + i) * 132 + kg];
                acc[i][0] += a * bv.x;
                acc[i][1] += a * bv.y;
                acc[i][2] += a * bv.z;
                acc[i][3] += a * bv.w;
            }
        }
    }
    {
        float* outH = out + (size_t)4 * NN;
#pragma unroll
        for (int i = 0; i < 8; i++) {
            int n = n0 + row0 + i;
            if (n < NN) {
                float4 v;
                v.x = acc[i][0]; v.y = acc[i][1]; v.z = acc[i][2]; v.w = acc[i][3];
                *(float4*)(outH + (size_t)n * 128 + col0) = v;
            }
        }
    }

    // ---- force normalize ----
    if (t < 64) {
        int n = n0 + t;
        if (n < NN) {
            float c = g_cnt[n];
            float inv = 1.0f / fmaxf(c, 1.0f);
            out[NN + (size_t)n * 3 + 0] = g_fsum[n * 3 + 0] * inv;
            out[NN + (size_t)n * 3 + 1] = g_fsum[n * 3 + 1] * inv;
            out[NN + (size_t)n * 3 + 2] = g_fsum[n * 3 + 2] * inv;
        }
    }
}

// ---------------------------------------------------------------------------
extern "C" void kernel_launch(void* const* d_in, const int* in_sizes, int n_in,
                              void* d_out, int out_size)
{
    const float* h          = (const float*)d_in[0];
    const float* coord_diff = (const float*)d_in[1];
    const int*   row        = (const int*)  d_in[2];
    const int*   col        = (const int*)  d_in[3];
    const float* We1 = (const float*)d_in[4];
    const float* be1 = (const float*)d_in[5];
    const float* We2 = (const float*)d_in[6];
    const float* be2 = (const float*)d_in[7];
    const float* Wn1 = (const float*)d_in[8];
    const float* bn1 = (const float*)d_in[9];
    const float* Wn2 = (const float*)d_in[10];
    const float* bn2 = (const float*)d_in[11];
    const float* Wc1 = (const float*)d_in[12];
    const float* bc1 = (const float*)d_in[13];
    const float* Wc2 = (const float*)d_in[14];
    const float* Wv1 = (const float*)d_in[15];
    const float* bv1 = (const float*)d_in[16];
    const float* Wv2 = (const float*)d_in[17];
    const float* bv2 = (const float*)d_in[18];
    float* out = (float*)d_out;

    void *aggp, *fsump, *cntp;
    cudaGetSymbolAddress(&aggp, g_agg);
    cudaGetSymbolAddress(&fsump, g_fsum);
    cudaGetSymbolAddress(&cntp, g_cnt);
    cudaMemsetAsync(aggp,  0, (size_t)NN * 128 * sizeof(float));
    cudaMemsetAsync(fsump, 0, (size_t)NN * 3 * sizeof(float));
    cudaMemsetAsync(cntp,  0, (size_t)NN * sizeof(float));

    prep_weights_f<<<384, 256>>>(We1, We2, Wc1, Wn1, Wv1);

    precompute_p<<<(NN + 63) / 64, 256, 36864>>>(h, bn1, bv1, Wv2, bv2, out);

    cudaFuncSetAttribute(edge_kernel_mma, cudaFuncAttributeMaxDynamicSharedMemorySize,
                         SMEM_EDGE_TOTAL);
    edge_kernel_mma<<<EE / 64, 256, SMEM_EDGE_TOTAL>>>(
        coord_diff, row, col, We1, be1, be2, bc1, Wc2);

    const size_t smN = (size_t)(4096 + 2112 + 8448) * sizeof(float);
    cudaFuncSetAttribute(node_kernel, cudaFuncAttributeMaxDynamicSharedMemorySize, (int)smN);
    node_kernel<<<(NN + 63) / 64, 256, smN>>>(Wn1, Wn2, bn2, out);
}